// round 13
// baseline (speedup 1.0000x reference)
#include <cuda_runtime.h>
#include <cstdint>

#define NPAPER 100000
#define NAUTH  50000
#define NINST  5000
#define NTOT   155000
#define SRCROWS 305000
#define ETOT   900000

// ---------------- device scratch (no allocations allowed) ----------------
__device__ __align__(256) float g_X[(size_t)NTOT*128];
__device__ __align__(256) float g_Y[(size_t)NTOT*128];
__device__ __align__(256) float g_KQV[(size_t)NTOT*384];
__device__ __align__(256) float g_KR[(size_t)SRCROWS*128];
__device__ __align__(256) float g_VR[(size_t)SRCROWS*128];
__device__ __align__(256) float g_DEN[(size_t)NTOT*8];
__device__ __align__(256) float g_AGG[(size_t)NTOT*128];
__device__ __align__(256) int g_OFF[NTOT + 1];   // CSR row offsets (by global dst)
__device__ __align__(256) int g_CUR[NTOT + 1];   // counts, then running cursors
__device__ __align__(256) int g_EIX[ETOT];       // CSR payload: KR/VR row index
__device__ int g_flags[3];

// ---------------- helpers ----------------

__device__ __forceinline__ float gelu_f(float x) {
    return 0.5f * x * (1.f + erff(x * 0.70710678118654752f));
}

__device__ __forceinline__ void split_tf32(float v, float& hi, float& lo) {
    uint32_t h, l;
    asm("cvt.rna.tf32.f32 %0, %1;" : "=r"(h) : "f"(v));
    float hf = __uint_as_float(h);
    asm("cvt.rna.tf32.f32 %0, %1;" : "=r"(l) : "f"(v - hf));
    hi = hf; lo = __uint_as_float(l);
}

__device__ __forceinline__ void mma_tf32(float c[4], const uint32_t a[4],
                                         uint32_t b0, uint32_t b1) {
    asm volatile(
        "mma.sync.aligned.m16n8k8.row.col.f32.tf32.tf32.f32 "
        "{%0,%1,%2,%3}, {%4,%5,%6,%7}, {%8,%9}, {%0,%1,%2,%3};"
        : "+f"(c[0]), "+f"(c[1]), "+f"(c[2]), "+f"(c[3])
        : "r"(a[0]), "r"(a[1]), "r"(a[2]), "r"(a[3]), "r"(b0), "r"(b1));
}

__device__ __forceinline__ int edge_src(const int* b, int e, int E, int lay) {
    return lay ? b[2 * e] : b[e];
}
__device__ __forceinline__ int edge_dst(const int* b, int e, int E, int lay) {
    return lay ? b[2 * e + 1] : b[E + e];
}

struct GB {  // per-node-type batched GEMM descriptors (z-indexed)
    const float* A[3];
    const float* W[3];
    const float* Bias[3];
    float*       C[3];
    const float* R[3];
    const float* S[3];
    const float* D[3];
    int M[3], K[3], lda[3], ldw[3], ldc[3];
    int H;
};

struct CSR {  // edge-tensor descriptors for CSR build
    const int* p0[5]; const int* p1[5];
    int flg[5];
    int ecnt[5]; int ebase[6];
    int droff[5]; int ndv[5];
    int kroff[5]; int nsv[5];
};

// ---------------- kernels ----------------

__global__ void resolve_kernel(const int* __restrict__ t01,
                               const int* __restrict__ t34a,
                               const int* __restrict__ t34b)
{
    __shared__ int s[8];
    if (threadIdx.x < 8) s[threadIdx.x] = 0;
    __syncthreads();
    int ah1 = 0, ah2 = 0, aodd = 0, bh1 = 0, bh2 = 0, bodd = 0, ch1 = 0, cev = 0;
    for (int i = threadIdx.x; i < 200000; i += blockDim.x) {
        int va = t34a[i], vb = t34b[i];
        if (i < 100000) { ah1 = max(ah1, va); bh1 = max(bh1, vb); }
        else            { ah2 = max(ah2, va); bh2 = max(bh2, vb); }
        if (i & 1) { aodd = max(aodd, va); bodd = max(bodd, vb); }
    }
    for (int i = threadIdx.x; i < 500000; i += blockDim.x) {
        int vc = t01[i];
        if (i < 250000) ch1 = max(ch1, vc);
        if (!(i & 1))   cev = max(cev, vc);
    }
    atomicMax(&s[0], ah1); atomicMax(&s[1], ah2); atomicMax(&s[2], aodd);
    atomicMax(&s[3], bh1); atomicMax(&s[4], bh2); atomicMax(&s[5], bodd);
    atomicMax(&s[6], ch1); atomicMax(&s[7], cev);
    __syncthreads();
    if (threadIdx.x == 0) {
        int m4 = min(min(s[0], s[1]), min(s[3], s[4]));
        int layE2 = (m4 >= 10000) ? 1 : 0;
        g_flags[2] = layE2;
        g_flags[1] = layE2 ? ((s[2] >= 10000) ? 1 : 0)
                           : ((s[1] >= 10000) ? 1 : 0);
        int srcmax = layE2 ? s[7] : s[6];
        g_flags[0] = (srcmax >= 60000) ? 1 : 0;
    }
}

__global__ void csr_zero(int* __restrict__ cnt) {
    int i = blockIdx.x * blockDim.x + threadIdx.x;
    if (i <= NTOT) cnt[i] = 0;
}

__global__ void csr_hist(CSR c, int* __restrict__ cnt) {
    int tid = blockIdx.x * blockDim.x + threadIdx.x;
    if (tid >= ETOT) return;
    int e = 0;
#pragma unroll
    for (int k = 1; k < 5; k++) if (tid >= c.ebase[k]) e = k;
    int i = tid - c.ebase[e], E = c.ecnt[e];
    const int* base = g_flags[c.flg[e]] ? c.p1[e] : c.p0[e];
    int lay = g_flags[2];
    int d = min(max(edge_dst(base, i, E, lay), 0), c.ndv[e] - 1);
    atomicAdd(&cnt[c.droff[e] + d], 1);
}

// Single-block exclusive scan over NTOT counts; writes OFF (prefix), resets
// CUR to prefix (scatter cursors), and OFF[NTOT] = total.
__global__ void csr_scan(int* __restrict__ cur, int* __restrict__ off) {
    __shared__ int ps[1024];
    const int t = threadIdx.x;
    const int chunk = (NTOT + 1023) >> 10;
    int lo = t * chunk, hi = min(NTOT, lo + chunk);
    int s = 0;
    for (int i = lo; i < hi; i++) s += cur[i];
    ps[t] = s;
    __syncthreads();
    for (int o = 1; o < 1024; o <<= 1) {
        int v = (t >= o) ? ps[t - o] : 0;
        __syncthreads();
        ps[t] += v;
        __syncthreads();
    }
    int run = ps[t] - s;
    for (int i = lo; i < hi; i++) {
        int cv = cur[i];
        off[i] = run; cur[i] = run;
        run += cv;
    }
    if (t == 1023) off[NTOT] = ps[1023];
}

__global__ void csr_scatter(CSR c, int* __restrict__ cur, int* __restrict__ eix) {
    int tid = blockIdx.x * blockDim.x + threadIdx.x;
    if (tid >= ETOT) return;
    int e = 0;
#pragma unroll
    for (int k = 1; k < 5; k++) if (tid >= c.ebase[k]) e = k;
    int i = tid - c.ebase[e], E = c.ecnt[e];
    const int* base = g_flags[c.flg[e]] ? c.p1[e] : c.p0[e];
    int lay = g_flags[2];
    int s = min(max(edge_src(base, i, E, lay), 0), c.nsv[e] - 1);
    int d = min(max(edge_dst(base, i, E, lay), 0), c.ndv[e] - 1);
    int pos = atomicAdd(&cur[c.droff[e] + d], 1);
    eix[pos] = c.kroff[e] + s;
}

// Batched (z = node type) C = epilogue(actA(A) @ W + bias) via 3xTF32 MMA.
__global__ __launch_bounds__(256)
void gemm_tf32(GB gb, int geluA, int reluO)
{
    const int z = blockIdx.z;
    const int M = gb.M[z];
    const int m0 = blockIdx.y * 128;
    if (m0 >= M) return;
    const int K = gb.K[z], lda = gb.lda[z], ldw = gb.ldw[z], ldc = gb.ldc[z];
    const float* __restrict__ A = gb.A[z];
    const float* __restrict__ W = gb.W[z];
    const float* __restrict__ bias = gb.Bias[z];
    const float* __restrict__ resid = gb.R[z];
    const float* __restrict__ Dn = gb.D[z];
    const int H = gb.H;
    float* __restrict__ C = gb.C[z];

    __shared__ float Ah[32][129], Al[32][129];
    __shared__ float Bh[64][33],  Bl[64][33];
    const int tid = threadIdx.x;
    const int lane = tid & 31, wid = tid >> 5;
    const int n0 = blockIdx.x * 64;
    const int moff = (wid & 3) * 32, noff = (wid >> 2) * 32;
    const int am = tid & 127, ak = (tid >> 7) * 16;
    const int bk = tid & 31,  bn = (tid >> 5) * 8;
    const bool arow_ok = (m0 + am < M);

    float c[2][4][4];
#pragma unroll
    for (int mt = 0; mt < 2; mt++)
#pragma unroll
        for (int nt = 0; nt < 4; nt++)
#pragma unroll
            for (int i = 0; i < 4; i++) c[mt][nt][i] = 0.f;

    float4 ra[4], rb[2];
    const float4 fz = make_float4(0.f, 0.f, 0.f, 0.f);

#define LDG_TILE(K0)                                                          \
    do {                                                                      \
        const float* ap = A + (size_t)(m0 + am) * lda + (K0) + ak;            \
        if (arow_ok) {                                                        \
            ra[0] = *(const float4*)(ap);      ra[1] = *(const float4*)(ap + 4); \
            ra[2] = *(const float4*)(ap + 8);  ra[3] = *(const float4*)(ap + 12);\
        } else { ra[0] = fz; ra[1] = fz; ra[2] = fz; ra[3] = fz; }             \
        if (Dn && arow_ok) {                                                  \
            float dn = __ldg(Dn + (size_t)(m0 + am) * H + (((K0) + ak) >> 4)); \
            float inv = 1.f / fmaxf(dn, 1e-16f);                              \
            _Pragma("unroll")                                                 \
            for (int j = 0; j < 4; j++) {                                     \
                ra[j].x *= inv; ra[j].y *= inv; ra[j].z *= inv; ra[j].w *= inv; \
            }                                                                 \
        }                                                                     \
        if (geluA) {                                                          \
            _Pragma("unroll")                                                 \
            for (int j = 0; j < 4; j++) {                                     \
                ra[j].x = gelu_f(ra[j].x); ra[j].y = gelu_f(ra[j].y);         \
                ra[j].z = gelu_f(ra[j].z); ra[j].w = gelu_f(ra[j].w);         \
            }                                                                 \
        }                                                                     \
        const float* bp = W + (size_t)((K0) + bk) * ldw + n0 + bn;            \
        rb[0] = *(const float4*)(bp); rb[1] = *(const float4*)(bp + 4);       \
    } while (0)

    LDG_TILE(0);
    const int niter = K >> 5;
    for (int it = 0; it < niter; it++) {
        __syncthreads();
#pragma unroll
        for (int j = 0; j < 4; j++) {
            float h, l;
            split_tf32(ra[j].x, h, l); Ah[ak + j*4 + 0][am] = h; Al[ak + j*4 + 0][am] = l;
            split_tf32(ra[j].y, h, l); Ah[ak + j*4 + 1][am] = h; Al[ak + j*4 + 1][am] = l;
            split_tf32(ra[j].z, h, l); Ah[ak + j*4 + 2][am] = h; Al[ak + j*4 + 2][am] = l;
            split_tf32(ra[j].w, h, l); Ah[ak + j*4 + 3][am] = h; Al[ak + j*4 + 3][am] = l;
        }
#pragma unroll
        for (int j = 0; j < 2; j++) {
            float h, l;
            split_tf32(rb[j].x, h, l); Bh[bn + j*4 + 0][bk] = h; Bl[bn + j*4 + 0][bk] = l;
            split_tf32(rb[j].y, h, l); Bh[bn + j*4 + 1][bk] = h; Bl[bn + j*4 + 1][bk] = l;
            split_tf32(rb[j].z, h, l); Bh[bn + j*4 + 2][bk] = h; Bl[bn + j*4 + 2][bk] = l;
            split_tf32(rb[j].w, h, l); Bh[bn + j*4 + 3][bk] = h; Bl[bn + j*4 + 3][bk] = l;
        }
        __syncthreads();
        if (it + 1 < niter) LDG_TILE((it + 1) << 5);
#pragma unroll
        for (int ks = 0; ks < 32; ks += 8) {
            const int kk = ks + (lane & 3);
            uint32_t ah[2][4], al[2][4];
#pragma unroll
            for (int mt = 0; mt < 2; mt++) {
                int r = moff + mt * 16 + (lane >> 2);
                ah[mt][0] = __float_as_uint(Ah[kk][r]);
                ah[mt][1] = __float_as_uint(Ah[kk][r + 8]);
                ah[mt][2] = __float_as_uint(Ah[kk + 4][r]);
                ah[mt][3] = __float_as_uint(Ah[kk + 4][r + 8]);
                al[mt][0] = __float_as_uint(Al[kk][r]);
                al[mt][1] = __float_as_uint(Al[kk][r + 8]);
                al[mt][2] = __float_as_uint(Al[kk + 4][r]);
                al[mt][3] = __float_as_uint(Al[kk + 4][r + 8]);
            }
#pragma unroll
            for (int nt = 0; nt < 4; nt++) {
                int bc = noff + nt * 8 + (lane >> 2);
                uint32_t bh0 = __float_as_uint(Bh[bc][kk]);
                uint32_t bh1 = __float_as_uint(Bh[bc][kk + 4]);
                uint32_t bl0 = __float_as_uint(Bl[bc][kk]);
                uint32_t bl1 = __float_as_uint(Bl[bc][kk + 4]);
#pragma unroll
                for (int mt = 0; mt < 2; mt++) {
                    mma_tf32(c[mt][nt], al[mt], bh0, bh1);
                    mma_tf32(c[mt][nt], ah[mt], bl0, bl1);
                    mma_tf32(c[mt][nt], ah[mt], bh0, bh1);
                }
            }
        }
    }
#undef LDG_TILE

    float sa = 0.f;
    if (resid) { float s = *gb.S[z]; sa = 1.f / (1.f + __expf(-s)); }
#pragma unroll
    for (int mt = 0; mt < 2; mt++) {
#pragma unroll
        for (int half = 0; half < 2; half++) {
            int cm = m0 + moff + mt * 16 + (lane >> 2) + half * 8;
            if (cm >= M) continue;
#pragma unroll
            for (int nt = 0; nt < 4; nt++) {
                int cn = n0 + noff + nt * 8 + (lane & 3) * 2;
                float v0 = c[mt][nt][half * 2 + 0] + bias[cn];
                float v1 = c[mt][nt][half * 2 + 1] + bias[cn + 1];
                if (reluO) { v0 = fmaxf(v0, 0.f); v1 = fmaxf(v1, 0.f); }
                if (resid) {
                    float2 r2 = *(const float2*)(resid + (size_t)cm * ldc + cn);
                    v0 = sa * v0 + (1.f - sa) * r2.x;
                    v1 = sa * v1 + (1.f - sa) * r2.y;
                }
                *(float2*)(C + (size_t)cm * ldc + cn) = make_float2(v0, v1);
            }
        }
    }
}

// Per-edge-type relation transform over source nodes, reading fused KQV.
// prel[h]*0.25 is folded into KR so the agg kernel does exp(q.kr) directly.
__global__ __launch_bounds__(256)
void relx_kernel(const float* __restrict__ KQV, int S, int foutp,
                 const float* __restrict__ krel, const float* __restrict__ vrel,
                 const float* __restrict__ prel,
                 float* __restrict__ KR, float* __restrict__ VR, int nsrc, int H)
{
    extern __shared__ float sh[];
    float* skr = sh;
    float* svr = sh + H * 256;
    for (int i = threadIdx.x; i < H * 256; i += blockDim.x) {
        skr[i] = krel[i]; svr[i] = vrel[i];
    }
    __syncthreads();
    const int fout = H << 4;
    int tid = blockIdx.x * blockDim.x + threadIdx.x;
    if (tid >= nsrc * fout) return;
    int n = tid / fout, c = tid - n * fout;
    int h = c >> 4, eo = c & 15;
    const float4* kin = (const float4*)(KQV + (size_t)n * S + h * 16);
    const float4* vin = (const float4*)(KQV + (size_t)n * S + 2 * foutp + h * 16);
    const float* km = skr + h * 256 + eo;
    const float* vm = svr + h * 256 + eo;
    float ak = 0.f, av = 0.f;
#pragma unroll
    for (int j = 0; j < 4; j++) {
        float4 k4 = kin[j], v4 = vin[j];
        const float* kmj = km + (j << 6);
        const float* vmj = vm + (j << 6);
        ak += k4.x * kmj[0] + k4.y * kmj[16] + k4.z * kmj[32] + k4.w * kmj[48];
        av += v4.x * vmj[0] + v4.y * vmj[16] + v4.z * vmj[32] + v4.w * vmj[48];
    }
    KR[tid] = ak * (__ldg(prel + h) * 0.25f);
    VR[tid] = av;
}

// CSR aggregation: one warp per global destination node. Q row loaded once;
// per incident edge: coalesced KR/VR row gather, 4-lane shfl dot per head,
// register accumulation. Single write of AGG row + DEN. Zero atomics.
__global__ __launch_bounds__(256)
void agg_csr_kernel(const float* __restrict__ KQV, int S, int fout, int H,
                    const float* __restrict__ KR, const float* __restrict__ VR,
                    float* __restrict__ DEN, float* __restrict__ AG)
{
    int w = (blockIdx.x * blockDim.x + threadIdx.x) >> 5;
    if (w >= NTOT) return;
    const int lane = threadIdx.x & 31;
    const int c4 = lane * 4;
    const bool act = c4 < fout;
    float4 q4 = act ? *(const float4*)(KQV + (size_t)w * S + fout + c4)
                    : make_float4(0.f, 0.f, 0.f, 0.f);
    float4 acc = make_float4(0.f, 0.f, 0.f, 0.f);
    float den = 0.f;
    int b = __ldg(&g_OFF[w]), e = __ldg(&g_OFF[w + 1]);
    for (int idx = b; idx < e; idx++) {
        int r = __ldg(&g_EIX[idx]);
        float4 k4 = act ? *(const float4*)(KR + (size_t)r * fout + c4)
                        : make_float4(0.f, 0.f, 0.f, 0.f);
        float p = q4.x * k4.x + q4.y * k4.y + q4.z * k4.z + q4.w * k4.w;
        p += __shfl_xor_sync(0xffffffffu, p, 1);
        p += __shfl_xor_sync(0xffffffffu, p, 2);
        float ex = __expf(p);
        if (act) {
            float4 v4 = *(const float4*)(VR + (size_t)r * fout + c4);
            acc.x += ex * v4.x; acc.y += ex * v4.y;
            acc.z += ex * v4.z; acc.w += ex * v4.w;
            den += ex;
        }
    }
    if (act) {
        *(float4*)(AG + (size_t)w * fout + c4) = acc;
        if ((lane & 3) == 0) DEN[(size_t)w * H + (lane >> 2)] = den;
    }
}

// ---------------- host orchestration ----------------

extern "C" void kernel_launch(void* const* d_in, const int* in_sizes, int n_in,
                              void* d_out, int out_size)
{
    static const long long ESIZE[30] = {
        25600000, 6400000, 320000,
        500000, 500000, 400000, 200000, 200000,
        32768, 128, 16384, 128, 8192, 128,
        147456, 1152, 10240, 10240, 40, 49152, 384, 3,
        73728, 576, 5120, 5120, 20, 12288, 192, 3
    };
    const void* P[30];
    bool got[30];
    for (int j = 0; j < 30; j++) { got[j] = false; P[j] = nullptr; }
    for (int i = 0; i < n_in; i++) {
        for (int j = 0; j < 30; j++) {
            if (!got[j] && (long long)in_sizes[i] == ESIZE[j]) {
                P[j] = d_in[i]; got[j] = true; break;
            }
        }
    }
    for (int j = 0; j < 30; j++) if (!got[j]) return;

    const float* x_in[3]  = {(const float*)P[0], (const float*)P[1], (const float*)P[2]};
    const int*   eptr[5]  = {(const int*)P[3], (const int*)P[4], (const int*)P[5],
                             (const int*)P[6], (const int*)P[7]};
    const float* lin_w[3] = {(const float*)P[8], (const float*)P[10], (const float*)P[12]};
    const float* lin_b[3] = {(const float*)P[9], (const float*)P[11], (const float*)P[13]};
    const float* kqv_w[2] = {(const float*)P[14], (const float*)P[22]};
    const float* kqv_b[2] = {(const float*)P[15], (const float*)P[23]};
    const float* krel[2]  = {(const float*)P[16], (const float*)P[24]};
    const float* vrel[2]  = {(const float*)P[17], (const float*)P[25]};
    const float* prel[2]  = {(const float*)P[18], (const float*)P[26]};
    const float* outw[2]  = {(const float*)P[19], (const float*)P[27]};
    const float* outb[2]  = {(const float*)P[20], (const float*)P[28]};
    const float* skipv[2] = {(const float*)P[21], (const float*)P[29]};

    float *X, *Y, *KQV, *KR, *VR, *Db, *AG;
    int *OFFp, *CURp, *EIXp;
#define GETSYM(p, s) do { if (cudaGetSymbolAddress((void**)&(p), s) != cudaSuccess) return; } while (0)
    GETSYM(X,  g_X);  GETSYM(Y,  g_Y);  GETSYM(KQV, g_KQV);
    GETSYM(KR, g_KR); GETSYM(VR, g_VR);
    GETSYM(Db, g_DEN); GETSYM(AG, g_AGG);
    GETSYM(OFFp, g_OFF); GETSYM(CURp, g_CUR); GETSYM(EIXp, g_EIX);
#undef GETSYM

    const int ntyp[3]  = {NPAPER, NAUTH, NINST};
    const int roff[3]  = {0, NPAPER, NPAPER + NAUTH};
    const int idim[3]  = {256, 128, 64};
    // EDGE_TYPES = [(1,0), (0,0), (0,1), (1,2), (2,1)]
    const int esrc[5]  = {1, 0, 0, 1, 2};
    const int edst[5]  = {0, 0, 1, 2, 1};
    const int ecnt[5]  = {250000, 250000, 200000, 100000, 100000};
    const int kroff[5] = {0, 50000, 150000, 250000, 300000};

    resolve_kernel<<<1, 1024>>>(eptr[0], eptr[3], eptr[4]);

    // ---- build CSR (dst -> KR-row list), shared by both layers ----
    {
        CSR c;
        int eb = 0;
        for (int e = 0; e < 5; e++) {
            c.p0[e] = eptr[e];
            c.p1[e] = (e == 0) ? eptr[1] : (e == 1) ? eptr[0]
                    : (e == 3) ? eptr[4] : (e == 4) ? eptr[3] : eptr[2];
            c.flg[e] = (e <= 2) ? 0 : 1;   // e==2 unambiguous (pri==alt)
            c.ecnt[e] = ecnt[e];
            c.ebase[e] = eb; eb += ecnt[e];
            c.droff[e] = roff[edst[e]]; c.ndv[e] = ntyp[edst[e]];
            c.kroff[e] = kroff[e];      c.nsv[e] = ntyp[esrc[e]];
        }
        c.ebase[5] = eb;
        csr_zero<<<(NTOT + 256) / 256, 256>>>(CURp);
        csr_hist<<<(ETOT + 255) / 256, 256>>>(c, CURp);
        csr_scan<<<1, 1024>>>(CURp, OFFp);
        csr_scatter<<<(ETOT + 255) / 256, 256>>>(c, CURp, EIXp);
    }

    const int MAXMB = (NPAPER + 127) / 128;   // 782

    // ---- input projections: X = relu(x @ lin_w + lin_b) ----
    {
        GB gb; gb.H = 1;
        for (int t = 0; t < 3; t++) {
            gb.A[t] = x_in[t];  gb.lda[t] = idim[t];
            gb.W[t] = lin_w[t]; gb.ldw[t] = 128;
            gb.Bias[t] = lin_b[t];
            gb.C[t] = X + (size_t)roff[t] * 128; gb.ldc[t] = 128;
            gb.R[t] = nullptr; gb.S[t] = nullptr; gb.D[t] = nullptr;
            gb.M[t] = ntyp[t]; gb.K[t] = idim[t];
        }
        gemm_tf32<<<dim3(2, MAXMB, 3), 256>>>(gb, 0, 1);
    }

    for (int li = 0; li < 2; li++) {
        const int H = li ? 4 : 8;
        const int fout = H * 16;
        const int S = 3 * fout;
        const float* Xin = li ? Y : X;

        // fused kqv projection, batched over types
        {
            GB gb; gb.H = 1;
            for (int t = 0; t < 3; t++) {
                gb.A[t] = Xin + (size_t)roff[t] * 128; gb.lda[t] = 128;
                gb.W[t] = kqv_w[li] + (size_t)t * 128 * S; gb.ldw[t] = S;
                gb.Bias[t] = kqv_b[li] + t * S;
                gb.C[t] = KQV + (size_t)roff[t] * S; gb.ldc[t] = S;
                gb.R[t] = nullptr; gb.S[t] = nullptr; gb.D[t] = nullptr;
                gb.M[t] = ntyp[t]; gb.K[t] = 128;
            }
            gemm_tf32<<<dim3(S / 64, MAXMB, 3), 256>>>(gb, 0, 0);
        }

        // per-edge-type relation transforms (prel*0.25 folded into KR)
        for (int e = 0; e < 5; e++) {
            int ns = ntyp[esrc[e]];
            int tot = ns * fout;
            size_t shb = (size_t)2 * H * 256 * sizeof(float);
            relx_kernel<<<(tot + 255) / 256, 256, shb>>>(
                KQV + (size_t)roff[esrc[e]] * S, S, fout,
                krel[li] + e * H * 256, vrel[li] + e * H * 256,
                prel[li] + e * H,
                KR + (size_t)kroff[e] * fout, VR + (size_t)kroff[e] * fout, ns, H);
        }

        // CSR aggregation: one launch covers all dsts and edge types
        agg_csr_kernel<<<(NTOT * 32 + 255) / 256, 256>>>(
            KQV, S, fout, H, KR, VR, Db, AG);

        // output projection (batched; normalizes A by den inside the load)
        if (li == 0) {
            GB gb; gb.H = H;
            for (int t = 0; t < 3; t++) {
                gb.A[t] = AG + (size_t)roff[t] * 128; gb.lda[t] = 128;
                gb.W[t] = outw[0] + (size_t)t * 128 * 128; gb.ldw[t] = 128;
                gb.Bias[t] = outb[0] + t * 128;
                gb.C[t] = Y + (size_t)roff[t] * 128; gb.ldc[t] = 128;
                gb.R[t] = Xin + (size_t)roff[t] * 128; gb.S[t] = skipv[0] + t;
                gb.D[t] = Db + (size_t)roff[t] * H;
                gb.M[t] = ntyp[t]; gb.K[t] = 128;
            }
            gemm_tf32<<<dim3(2, MAXMB, 3), 256>>>(gb, 1, 0);
        } else {
            const size_t ooff[3] = {0, (size_t)NPAPER * 64, (size_t)(NPAPER + NAUTH) * 64};
            const long long need[3] = {6400000LL, 9600000LL, 9920000LL};
            GB gb; gb.H = H;
            for (int t = 0; t < 3; t++) {
                gb.A[t] = AG + (size_t)roff[t] * 64; gb.lda[t] = 64;
                gb.W[t] = outw[1] + (size_t)t * 64 * 64; gb.ldw[t] = 64;
                gb.Bias[t] = outb[1] + t * 64;
                gb.C[t] = (float*)d_out + ooff[t]; gb.ldc[t] = 64;
                gb.R[t] = nullptr; gb.S[t] = nullptr;
                gb.D[t] = Db + (size_t)roff[t] * H;
                gb.M[t] = ((long long)out_size >= need[t]) ? ntyp[t] : 0;
                gb.K[t] = 64;
            }
            gemm_tf32<<<dim3(1, MAXMB, 3), 256>>>(gb, 1, 0);
        }
    }
}

// round 14
// speedup vs baseline: 1.0833x; 1.0833x over previous
#include <cuda_runtime.h>
#include <cstdint>

#define NPAPER 100000
#define NAUTH  50000
#define NINST  5000
#define NTOT   155000
#define SRCROWS 305000
#define ETOT   900000
#define NBLK   152   // ceil(NTOT/1024)

// ---------------- device scratch (no allocations allowed) ----------------
__device__ __align__(256) float g_X[(size_t)NTOT*128];
__device__ __align__(256) float g_Y[(size_t)NTOT*128];
__device__ __align__(256) float g_KQV[(size_t)NTOT*384];
__device__ __align__(256) float g_KR[(size_t)SRCROWS*128];
__device__ __align__(256) float g_VR[(size_t)SRCROWS*128];
__device__ __align__(256) float g_DEN[(size_t)NTOT*8];
__device__ __align__(256) float g_AGG[(size_t)NTOT*128];
__device__ __align__(256) int g_OFF[NTOT + 1];   // CSR row offsets (by global dst)
__device__ __align__(256) int g_CUR[NTOT + 1];   // counts, then running cursors
__device__ __align__(256) int g_EIX[ETOT];       // CSR payload: KR/VR row index
__device__ __align__(256) int g_BS[256];         // block sums for scan
__device__ int g_flags[3];

// ---------------- helpers ----------------

__device__ __forceinline__ float gelu_f(float x) {
    return 0.5f * x * (1.f + erff(x * 0.70710678118654752f));
}

__device__ __forceinline__ void split_tf32(float v, float& hi, float& lo) {
    uint32_t h, l;
    asm("cvt.rna.tf32.f32 %0, %1;" : "=r"(h) : "f"(v));
    float hf = __uint_as_float(h);
    asm("cvt.rna.tf32.f32 %0, %1;" : "=r"(l) : "f"(v - hf));
    hi = hf; lo = __uint_as_float(l);
}

__device__ __forceinline__ void mma_tf32(float c[4], const uint32_t a[4],
                                         uint32_t b0, uint32_t b1) {
    asm volatile(
        "mma.sync.aligned.m16n8k8.row.col.f32.tf32.tf32.f32 "
        "{%0,%1,%2,%3}, {%4,%5,%6,%7}, {%8,%9}, {%0,%1,%2,%3};"
        : "+f"(c[0]), "+f"(c[1]), "+f"(c[2]), "+f"(c[3])
        : "r"(a[0]), "r"(a[1]), "r"(a[2]), "r"(a[3]), "r"(b0), "r"(b1));
}

__device__ __forceinline__ int edge_src(const int* b, int e, int E, int lay) {
    return lay ? b[2 * e] : b[e];
}
__device__ __forceinline__ int edge_dst(const int* b, int e, int E, int lay) {
    return lay ? b[2 * e + 1] : b[E + e];
}

struct GB {
    const float* A[3];
    const float* W[3];
    const float* Bias[3];
    float*       C[3];
    const float* R[3];
    const float* S[3];
    const float* D[3];
    int M[3], K[3], lda[3], ldw[3], ldc[3];
    int H;
};

struct CSR {
    const int* p0[5]; const int* p1[5];
    int flg[5];
    int ecnt[5]; int ebase[6];
    int droff[5]; int ndv[5];
    int kroff[5]; int nsv[5];
};

// ---------------- kernels ----------------

__global__ void resolve_kernel(const int* __restrict__ t01,
                               const int* __restrict__ t34a,
                               const int* __restrict__ t34b)
{
    __shared__ int s[8];
    if (threadIdx.x < 8) s[threadIdx.x] = 0;
    __syncthreads();
    int ah1 = 0, ah2 = 0, aodd = 0, bh1 = 0, bh2 = 0, bodd = 0, ch1 = 0, cev = 0;
    for (int i = threadIdx.x; i < 200000; i += blockDim.x) {
        int va = t34a[i], vb = t34b[i];
        if (i < 100000) { ah1 = max(ah1, va); bh1 = max(bh1, vb); }
        else            { ah2 = max(ah2, va); bh2 = max(bh2, vb); }
        if (i & 1) { aodd = max(aodd, va); bodd = max(bodd, vb); }
    }
    for (int i = threadIdx.x; i < 500000; i += blockDim.x) {
        int vc = t01[i];
        if (i < 250000) ch1 = max(ch1, vc);
        if (!(i & 1))   cev = max(cev, vc);
    }
    atomicMax(&s[0], ah1); atomicMax(&s[1], ah2); atomicMax(&s[2], aodd);
    atomicMax(&s[3], bh1); atomicMax(&s[4], bh2); atomicMax(&s[5], bodd);
    atomicMax(&s[6], ch1); atomicMax(&s[7], cev);
    __syncthreads();
    if (threadIdx.x == 0) {
        int m4 = min(min(s[0], s[1]), min(s[3], s[4]));
        int layE2 = (m4 >= 10000) ? 1 : 0;
        g_flags[2] = layE2;
        g_flags[1] = layE2 ? ((s[2] >= 10000) ? 1 : 0)
                           : ((s[1] >= 10000) ? 1 : 0);
        int srcmax = layE2 ? s[7] : s[6];
        g_flags[0] = (srcmax >= 60000) ? 1 : 0;
    }
}

__global__ void csr_zero(int* __restrict__ cnt) {
    int i = blockIdx.x * blockDim.x + threadIdx.x;
    if (i <= NTOT) cnt[i] = 0;
}

__global__ void csr_hist(CSR c, int* __restrict__ cnt) {
    int tid = blockIdx.x * blockDim.x + threadIdx.x;
    if (tid >= ETOT) return;
    int e = 0;
#pragma unroll
    for (int k = 1; k < 5; k++) if (tid >= c.ebase[k]) e = k;
    int i = tid - c.ebase[e], E = c.ecnt[e];
    const int* base = g_flags[c.flg[e]] ? c.p1[e] : c.p0[e];
    int lay = g_flags[2];
    int d = min(max(edge_dst(base, i, E, lay), 0), c.ndv[e] - 1);
    atomicAdd(&cnt[c.droff[e] + d], 1);
}

// Phase A: per-block sums of counts.
__global__ void csr_reduce(const int* __restrict__ cnt, int* __restrict__ bsum) {
    __shared__ int sh[1024];
    int i = blockIdx.x * 1024 + threadIdx.x;
    sh[threadIdx.x] = (i < NTOT) ? cnt[i] : 0;
    __syncthreads();
    for (int o = 512; o > 0; o >>= 1) {
        if (threadIdx.x < o) sh[threadIdx.x] += sh[threadIdx.x + o];
        __syncthreads();
    }
    if (threadIdx.x == 0) bsum[blockIdx.x] = sh[0];
}

// Phase B: exclusive scan of block sums (<=256 blocks), sets OFF[NTOT]=total.
__global__ void csr_bscan(int* __restrict__ bsum, int* __restrict__ off, int nb) {
    __shared__ int sh[256];
    int t = threadIdx.x;
    int v = (t < nb) ? bsum[t] : 0;
    sh[t] = v;
    __syncthreads();
    for (int o = 1; o < 256; o <<= 1) {
        int u = (t >= o) ? sh[t - o] : 0;
        __syncthreads();
        sh[t] += u;
        __syncthreads();
    }
    if (t < nb) bsum[t] = sh[t] - v;
    if (t == 255) off[NTOT] = sh[255];
}

// Phase C: per-block exclusive scan + block offset; writes OFF and resets CUR.
__global__ void csr_apply(int* __restrict__ cnt, const int* __restrict__ bsum,
                          int* __restrict__ off) {
    __shared__ int sh[1024];
    int i = blockIdx.x * 1024 + threadIdx.x;
    int v = (i < NTOT) ? cnt[i] : 0;
    sh[threadIdx.x] = v;
    __syncthreads();
    for (int o = 1; o < 1024; o <<= 1) {
        int u = (threadIdx.x >= o) ? sh[threadIdx.x - o] : 0;
        __syncthreads();
        sh[threadIdx.x] += u;
        __syncthreads();
    }
    if (i < NTOT) {
        int ex = bsum[blockIdx.x] + sh[threadIdx.x] - v;
        off[i] = ex; cnt[i] = ex;   // cnt buffer becomes scatter cursor
    }
}

__global__ void csr_scatter(CSR c, int* __restrict__ cur, int* __restrict__ eix) {
    int tid = blockIdx.x * blockDim.x + threadIdx.x;
    if (tid >= ETOT) return;
    int e = 0;
#pragma unroll
    for (int k = 1; k < 5; k++) if (tid >= c.ebase[k]) e = k;
    int i = tid - c.ebase[e], E = c.ecnt[e];
    const int* base = g_flags[c.flg[e]] ? c.p1[e] : c.p0[e];
    int lay = g_flags[2];
    int s = min(max(edge_src(base, i, E, lay), 0), c.nsv[e] - 1);
    int d = min(max(edge_dst(base, i, E, lay), 0), c.ndv[e] - 1);
    int pos = atomicAdd(&cur[c.droff[e] + d], 1);
    eix[pos] = c.kroff[e] + s;
}

// Batched (z = node type) C = epilogue(actA(A) @ W + bias) via 3xTF32 MMA.
__global__ __launch_bounds__(256)
void gemm_tf32(GB gb, int geluA, int reluO)
{
    const int z = blockIdx.z;
    const int M = gb.M[z];
    const int m0 = blockIdx.y * 128;
    if (m0 >= M) return;
    const int K = gb.K[z], lda = gb.lda[z], ldw = gb.ldw[z], ldc = gb.ldc[z];
    const float* __restrict__ A = gb.A[z];
    const float* __restrict__ W = gb.W[z];
    const float* __restrict__ bias = gb.Bias[z];
    const float* __restrict__ resid = gb.R[z];
    const float* __restrict__ Dn = gb.D[z];
    const int H = gb.H;
    float* __restrict__ C = gb.C[z];

    __shared__ float Ah[32][129], Al[32][129];
    __shared__ float Bh[64][33],  Bl[64][33];
    const int tid = threadIdx.x;
    const int lane = tid & 31, wid = tid >> 5;
    const int n0 = blockIdx.x * 64;
    const int moff = (wid & 3) * 32, noff = (wid >> 2) * 32;
    const int am = tid & 127, ak = (tid >> 7) * 16;
    const int bk = tid & 31,  bn = (tid >> 5) * 8;
    const bool arow_ok = (m0 + am < M);

    float c[2][4][4];
#pragma unroll
    for (int mt = 0; mt < 2; mt++)
#pragma unroll
        for (int nt = 0; nt < 4; nt++)
#pragma unroll
            for (int i = 0; i < 4; i++) c[mt][nt][i] = 0.f;

    float4 ra[4], rb[2];
    const float4 fz = make_float4(0.f, 0.f, 0.f, 0.f);

#define LDG_TILE(K0)                                                          \
    do {                                                                      \
        const float* ap = A + (size_t)(m0 + am) * lda + (K0) + ak;            \
        if (arow_ok) {                                                        \
            ra[0] = *(const float4*)(ap);      ra[1] = *(const float4*)(ap + 4); \
            ra[2] = *(const float4*)(ap + 8);  ra[3] = *(const float4*)(ap + 12);\
        } else { ra[0] = fz; ra[1] = fz; ra[2] = fz; ra[3] = fz; }             \
        if (Dn && arow_ok) {                                                  \
            float dn = __ldg(Dn + (size_t)(m0 + am) * H + (((K0) + ak) >> 4)); \
            float inv = 1.f / fmaxf(dn, 1e-16f);                              \
            _Pragma("unroll")                                                 \
            for (int j = 0; j < 4; j++) {                                     \
                ra[j].x *= inv; ra[j].y *= inv; ra[j].z *= inv; ra[j].w *= inv; \
            }                                                                 \
        }                                                                     \
        if (geluA) {                                                          \
            _Pragma("unroll")                                                 \
            for (int j = 0; j < 4; j++) {                                     \
                ra[j].x = gelu_f(ra[j].x); ra[j].y = gelu_f(ra[j].y);         \
                ra[j].z = gelu_f(ra[j].z); ra[j].w = gelu_f(ra[j].w);         \
            }                                                                 \
        }                                                                     \
        const float* bp = W + (size_t)((K0) + bk) * ldw + n0 + bn;            \
        rb[0] = *(const float4*)(bp); rb[1] = *(const float4*)(bp + 4);       \
    } while (0)

    LDG_TILE(0);
    const int niter = K >> 5;
    for (int it = 0; it < niter; it++) {
        __syncthreads();
#pragma unroll
        for (int j = 0; j < 4; j++) {
            float h, l;
            split_tf32(ra[j].x, h, l); Ah[ak + j*4 + 0][am] = h; Al[ak + j*4 + 0][am] = l;
            split_tf32(ra[j].y, h, l); Ah[ak + j*4 + 1][am] = h; Al[ak + j*4 + 1][am] = l;
            split_tf32(ra[j].z, h, l); Ah[ak + j*4 + 2][am] = h; Al[ak + j*4 + 2][am] = l;
            split_tf32(ra[j].w, h, l); Ah[ak + j*4 + 3][am] = h; Al[ak + j*4 + 3][am] = l;
        }
#pragma unroll
        for (int j = 0; j < 2; j++) {
            float h, l;
            split_tf32(rb[j].x, h, l); Bh[bn + j*4 + 0][bk] = h; Bl[bn + j*4 + 0][bk] = l;
            split_tf32(rb[j].y, h, l); Bh[bn + j*4 + 1][bk] = h; Bl[bn + j*4 + 1][bk] = l;
            split_tf32(rb[j].z, h, l); Bh[bn + j*4 + 2][bk] = h; Bl[bn + j*4 + 2][bk] = l;
            split_tf32(rb[j].w, h, l); Bh[bn + j*4 + 3][bk] = h; Bl[bn + j*4 + 3][bk] = l;
        }
        __syncthreads();
        if (it + 1 < niter) LDG_TILE((it + 1) << 5);
#pragma unroll
        for (int ks = 0; ks < 32; ks += 8) {
            const int kk = ks + (lane & 3);
            uint32_t ah[2][4], al[2][4];
#pragma unroll
            for (int mt = 0; mt < 2; mt++) {
                int r = moff + mt * 16 + (lane >> 2);
                ah[mt][0] = __float_as_uint(Ah[kk][r]);
                ah[mt][1] = __float_as_uint(Ah[kk][r + 8]);
                ah[mt][2] = __float_as_uint(Ah[kk + 4][r]);
                ah[mt][3] = __float_as_uint(Ah[kk + 4][r + 8]);
                al[mt][0] = __float_as_uint(Al[kk][r]);
                al[mt][1] = __float_as_uint(Al[kk][r + 8]);
                al[mt][2] = __float_as_uint(Al[kk + 4][r]);
                al[mt][3] = __float_as_uint(Al[kk + 4][r + 8]);
            }
#pragma unroll
            for (int nt = 0; nt < 4; nt++) {
                int bc = noff + nt * 8 + (lane >> 2);
                uint32_t bh0 = __float_as_uint(Bh[bc][kk]);
                uint32_t bh1 = __float_as_uint(Bh[bc][kk + 4]);
                uint32_t bl0 = __float_as_uint(Bl[bc][kk]);
                uint32_t bl1 = __float_as_uint(Bl[bc][kk + 4]);
#pragma unroll
                for (int mt = 0; mt < 2; mt++) {
                    mma_tf32(c[mt][nt], al[mt], bh0, bh1);
                    mma_tf32(c[mt][nt], ah[mt], bl0, bl1);
                    mma_tf32(c[mt][nt], ah[mt], bh0, bh1);
                }
            }
        }
    }
#undef LDG_TILE

    float sa = 0.f;
    if (resid) { float s = *gb.S[z]; sa = 1.f / (1.f + __expf(-s)); }
#pragma unroll
    for (int mt = 0; mt < 2; mt++) {
#pragma unroll
        for (int half = 0; half < 2; half++) {
            int cm = m0 + moff + mt * 16 + (lane >> 2) + half * 8;
            if (cm >= M) continue;
#pragma unroll
            for (int nt = 0; nt < 4; nt++) {
                int cn = n0 + noff + nt * 8 + (lane & 3) * 2;
                float v0 = c[mt][nt][half * 2 + 0] + bias[cn];
                float v1 = c[mt][nt][half * 2 + 1] + bias[cn + 1];
                if (reluO) { v0 = fmaxf(v0, 0.f); v1 = fmaxf(v1, 0.f); }
                if (resid) {
                    float2 r2 = *(const float2*)(resid + (size_t)cm * ldc + cn);
                    v0 = sa * v0 + (1.f - sa) * r2.x;
                    v1 = sa * v1 + (1.f - sa) * r2.y;
                }
                *(float2*)(C + (size_t)cm * ldc + cn) = make_float2(v0, v1);
            }
        }
    }
}

// Per-edge-type relation transform; prel[h]*0.25 folded into KR.
__global__ __launch_bounds__(256)
void relx_kernel(const float* __restrict__ KQV, int S, int foutp,
                 const float* __restrict__ krel, const float* __restrict__ vrel,
                 const float* __restrict__ prel,
                 float* __restrict__ KR, float* __restrict__ VR, int nsrc, int H)
{
    extern __shared__ float sh[];
    float* skr = sh;
    float* svr = sh + H * 256;
    for (int i = threadIdx.x; i < H * 256; i += blockDim.x) {
        skr[i] = krel[i]; svr[i] = vrel[i];
    }
    __syncthreads();
    const int fout = H << 4;
    int tid = blockIdx.x * blockDim.x + threadIdx.x;
    if (tid >= nsrc * fout) return;
    int n = tid / fout, c = tid - n * fout;
    int h = c >> 4, eo = c & 15;
    const float4* kin = (const float4*)(KQV + (size_t)n * S + h * 16);
    const float4* vin = (const float4*)(KQV + (size_t)n * S + 2 * foutp + h * 16);
    const float* km = skr + h * 256 + eo;
    const float* vm = svr + h * 256 + eo;
    float ak = 0.f, av = 0.f;
#pragma unroll
    for (int j = 0; j < 4; j++) {
        float4 k4 = kin[j], v4 = vin[j];
        const float* kmj = km + (j << 6);
        const float* vmj = vm + (j << 6);
        ak += k4.x * kmj[0] + k4.y * kmj[16] + k4.z * kmj[32] + k4.w * kmj[48];
        av += v4.x * vmj[0] + v4.y * vmj[16] + v4.z * vmj[32] + v4.w * vmj[48];
    }
    KR[tid] = ak * (__ldg(prel + h) * 0.25f);
    VR[tid] = av;
}

// CSR aggregation: dpw destinations per warp (1 for fout=128, 2 for fout=64).
// Each sub-warp of fout/4 lanes covers one dst: Q row loaded once, per-edge
// coalesced KR/VR gathers, 4-lane shfl dot per head, register accumulation.
__global__ __launch_bounds__(256)
void agg_csr_kernel(const float* __restrict__ KQV, int S, int fout, int H, int dpw,
                    const float* __restrict__ KR, const float* __restrict__ VR,
                    float* __restrict__ DEN, float* __restrict__ AG)
{
    int gw = (blockIdx.x * blockDim.x + threadIdx.x) >> 5;
    const int lane = threadIdx.x & 31;
    const int sub = (dpw == 2) ? (lane >> 4) : 0;
    int w = gw * dpw + sub;
    if (w >= NTOT) return;
    const int li = (dpw == 2) ? (lane & 15) : lane;
    const int c4 = li * 4;
    const unsigned mask = (dpw == 2) ? (0xFFFFu << (sub * 16)) : 0xFFFFFFFFu;
    float4 q4 = *(const float4*)(KQV + (size_t)w * S + fout + c4);
    float4 acc = make_float4(0.f, 0.f, 0.f, 0.f);
    float den = 0.f;
    int b = __ldg(&g_OFF[w]), e = __ldg(&g_OFF[w + 1]);
    for (int idx = b; idx < e; idx++) {
        int r = __ldg(&g_EIX[idx]);
        float4 k4 = *(const float4*)(KR + (size_t)r * fout + c4);
        float p = q4.x * k4.x + q4.y * k4.y + q4.z * k4.z + q4.w * k4.w;
        p += __shfl_xor_sync(mask, p, 1);
        p += __shfl_xor_sync(mask, p, 2);
        float ex = __expf(p);
        float4 v4 = *(const float4*)(VR + (size_t)r * fout + c4);
        acc.x += ex * v4.x; acc.y += ex * v4.y;
        acc.z += ex * v4.z; acc.w += ex * v4.w;
        den += ex;
    }
    *(float4*)(AG + (size_t)w * fout + c4) = acc;
    if ((li & 3) == 0) DEN[(size_t)w * H + (li >> 2)] = den;
}

// ---------------- host orchestration ----------------

extern "C" void kernel_launch(void* const* d_in, const int* in_sizes, int n_in,
                              void* d_out, int out_size)
{
    static const long long ESIZE[30] = {
        25600000, 6400000, 320000,
        500000, 500000, 400000, 200000, 200000,
        32768, 128, 16384, 128, 8192, 128,
        147456, 1152, 10240, 10240, 40, 49152, 384, 3,
        73728, 576, 5120, 5120, 20, 12288, 192, 3
    };
    const void* P[30];
    bool got[30];
    for (int j = 0; j < 30; j++) { got[j] = false; P[j] = nullptr; }
    for (int i = 0; i < n_in; i++) {
        for (int j = 0; j < 30; j++) {
            if (!got[j] && (long long)in_sizes[i] == ESIZE[j]) {
                P[j] = d_in[i]; got[j] = true; break;
            }
        }
    }
    for (int j = 0; j < 30; j++) if (!got[j]) return;

    const float* x_in[3]  = {(const float*)P[0], (const float*)P[1], (const float*)P[2]};
    const int*   eptr[5]  = {(const int*)P[3], (const int*)P[4], (const int*)P[5],
                             (const int*)P[6], (const int*)P[7]};
    const float* lin_w[3] = {(const float*)P[8], (const float*)P[10], (const float*)P[12]};
    const float* lin_b[3] = {(const float*)P[9], (const float*)P[11], (const float*)P[13]};
    const float* kqv_w[2] = {(const float*)P[14], (const float*)P[22]};
    const float* kqv_b[2] = {(const float*)P[15], (const float*)P[23]};
    const float* krel[2]  = {(const float*)P[16], (const float*)P[24]};
    const float* vrel[2]  = {(const float*)P[17], (const float*)P[25]};
    const float* prel[2]  = {(const float*)P[18], (const float*)P[26]};
    const float* outw[2]  = {(const float*)P[19], (const float*)P[27]};
    const float* outb[2]  = {(const float*)P[20], (const float*)P[28]};
    const float* skipv[2] = {(const float*)P[21], (const float*)P[29]};

    float *X, *Y, *KQV, *KR, *VR, *Db, *AG;
    int *OFFp, *CURp, *EIXp, *BSp;
#define GETSYM(p, s) do { if (cudaGetSymbolAddress((void**)&(p), s) != cudaSuccess) return; } while (0)
    GETSYM(X,  g_X);  GETSYM(Y,  g_Y);  GETSYM(KQV, g_KQV);
    GETSYM(KR, g_KR); GETSYM(VR, g_VR);
    GETSYM(Db, g_DEN); GETSYM(AG, g_AGG);
    GETSYM(OFFp, g_OFF); GETSYM(CURp, g_CUR); GETSYM(EIXp, g_EIX); GETSYM(BSp, g_BS);
#undef GETSYM

    const int ntyp[3]  = {NPAPER, NAUTH, NINST};
    const int roff[3]  = {0, NPAPER, NPAPER + NAUTH};
    const int idim[3]  = {256, 128, 64};
    // EDGE_TYPES = [(1,0), (0,0), (0,1), (1,2), (2,1)]
    const int esrc[5]  = {1, 0, 0, 1, 2};
    const int edst[5]  = {0, 0, 1, 2, 1};
    const int ecnt[5]  = {250000, 250000, 200000, 100000, 100000};
    const int kroff[5] = {0, 50000, 150000, 250000, 300000};

    resolve_kernel<<<1, 1024>>>(eptr[0], eptr[3], eptr[4]);

    // ---- build CSR (dst -> KR-row list), shared by both layers ----
    {
        CSR c;
        int eb = 0;
        for (int e = 0; e < 5; e++) {
            c.p0[e] = eptr[e];
            c.p1[e] = (e == 0) ? eptr[1] : (e == 1) ? eptr[0]
                    : (e == 3) ? eptr[4] : (e == 4) ? eptr[3] : eptr[2];
            c.flg[e] = (e <= 2) ? 0 : 1;
            c.ecnt[e] = ecnt[e];
            c.ebase[e] = eb; eb += ecnt[e];
            c.droff[e] = roff[edst[e]]; c.ndv[e] = ntyp[edst[e]];
            c.kroff[e] = kroff[e];      c.nsv[e] = ntyp[esrc[e]];
        }
        c.ebase[5] = eb;
        csr_zero<<<(NTOT + 256) / 256, 256>>>(CURp);
        csr_hist<<<(ETOT + 255) / 256, 256>>>(c, CURp);
        csr_reduce<<<NBLK, 1024>>>(CURp, BSp);
        csr_bscan<<<1, 256>>>(BSp, OFFp, NBLK);
        csr_apply<<<NBLK, 1024>>>(CURp, BSp, OFFp);
        csr_scatter<<<(ETOT + 255) / 256, 256>>>(c, CURp, EIXp);
    }

    const int MAXMB = (NPAPER + 127) / 128;   // 782

    // ---- input projections: X = relu(x @ lin_w + lin_b) ----
    {
        GB gb; gb.H = 1;
        for (int t = 0; t < 3; t++) {
            gb.A[t] = x_in[t];  gb.lda[t] = idim[t];
            gb.W[t] = lin_w[t]; gb.ldw[t] = 128;
            gb.Bias[t] = lin_b[t];
            gb.C[t] = X + (size_t)roff[t] * 128; gb.ldc[t] = 128;
            gb.R[t] = nullptr; gb.S[t] = nullptr; gb.D[t] = nullptr;
            gb.M[t] = ntyp[t]; gb.K[t] = idim[t];
        }
        gemm_tf32<<<dim3(2, MAXMB, 3), 256>>>(gb, 0, 1);
    }

    for (int li = 0; li < 2; li++) {
        const int H = li ? 4 : 8;
        const int fout = H * 16;
        const int S = 3 * fout;
        const int dpw = li ? 2 : 1;
        const float* Xin = li ? Y : X;

        // fused kqv projection, batched over types
        {
            GB gb; gb.H = 1;
            for (int t = 0; t < 3; t++) {
                gb.A[t] = Xin + (size_t)roff[t] * 128; gb.lda[t] = 128;
                gb.W[t] = kqv_w[li] + (size_t)t * 128 * S; gb.ldw[t] = S;
                gb.Bias[t] = kqv_b[li] + t * S;
                gb.C[t] = KQV + (size_t)roff[t] * S; gb.ldc[t] = S;
                gb.R[t] = nullptr; gb.S[t] = nullptr; gb.D[t] = nullptr;
                gb.M[t] = ntyp[t]; gb.K[t] = 128;
            }
            gemm_tf32<<<dim3(S / 64, MAXMB, 3), 256>>>(gb, 0, 0);
        }

        // per-edge-type relation transforms (prel*0.25 folded into KR)
        for (int e = 0; e < 5; e++) {
            int ns = ntyp[esrc[e]];
            int tot = ns * fout;
            size_t shb = (size_t)2 * H * 256 * sizeof(float);
            relx_kernel<<<(tot + 255) / 256, 256, shb>>>(
                KQV + (size_t)roff[esrc[e]] * S, S, fout,
                krel[li] + e * H * 256, vrel[li] + e * H * 256,
                prel[li] + e * H,
                KR + (size_t)kroff[e] * fout, VR + (size_t)kroff[e] * fout, ns, H);
        }

        // CSR aggregation (dpw dsts per warp)
        {
            int nw = (NTOT + dpw - 1) / dpw;
            agg_csr_kernel<<<(nw * 32 + 255) / 256, 256>>>(
                KQV, S, fout, H, dpw, KR, VR, Db, AG);
        }

        // output projection (batched; normalizes A by den inside the load)
        if (li == 0) {
            GB gb; gb.H = H;
            for (int t = 0; t < 3; t++) {
                gb.A[t] = AG + (size_t)roff[t] * 128; gb.lda[t] = 128;
                gb.W[t] = outw[0] + (size_t)t * 128 * 128; gb.ldw[t] = 128;
                gb.Bias[t] = outb[0] + t * 128;
                gb.C[t] = Y + (size_t)roff[t] * 128; gb.ldc[t] = 128;
                gb.R[t] = Xin + (size_t)roff[t] * 128; gb.S[t] = skipv[0] + t;
                gb.D[t] = Db + (size_t)roff[t] * H;
                gb.M[t] = ntyp[t]; gb.K[t] = 128;
            }
            gemm_tf32<<<dim3(2, MAXMB, 3), 256>>>(gb, 1, 0);
        } else {
            const size_t ooff[3] = {0, (size_t)NPAPER * 64, (size_t)(NPAPER + NAUTH) * 64};
            const long long need[3] = {6400000LL, 9600000LL, 9920000LL};
            GB gb; gb.H = H;
            for (int t = 0; t < 3; t++) {
                gb.A[t] = AG + (size_t)roff[t] * 64; gb.lda[t] = 64;
                gb.W[t] = outw[1] + (size_t)t * 64 * 64; gb.ldw[t] = 64;
                gb.Bias[t] = outb[1] + t * 64;
                gb.C[t] = (float*)d_out + ooff[t]; gb.ldc[t] = 64;
                gb.R[t] = nullptr; gb.S[t] = nullptr;
                gb.D[t] = Db + (size_t)roff[t] * H;
                gb.M[t] = ((long long)out_size >= need[t]) ? ntyp[t] : 0;
                gb.K[t] = 64;
            }
            gemm_tf32<<<dim3(1, MAXMB, 3), 256>>>(gb, 1, 0);
        }
    }
}

// round 15
// speedup vs baseline: 1.5108x; 1.3947x over previous
#include <cuda_runtime.h>
#include <cuda_bf16.h>
#include <cstdint>

#define NPAPER 100000
#define NAUTH  50000
#define NINST  5000
#define NTOT   155000
#define SRCROWS 305000
#define ETOT   900000
#define NBLK   152   // ceil(NTOT/1024)

// ---------------- device scratch (no allocations allowed) ----------------
__device__ __align__(256) float g_X[(size_t)NTOT*128];
__device__ __align__(256) float g_Y[(size_t)NTOT*128];
__device__ __align__(256) float g_KQV[(size_t)NTOT*384];
__device__ __align__(256) float g_KR[(size_t)SRCROWS*128];
__device__ __align__(256) float g_VR[(size_t)SRCROWS*128];
__device__ __align__(256) float g_DEN[(size_t)NTOT*8];
__device__ __align__(256) float g_AGG[(size_t)NTOT*128];
__device__ __align__(256) int g_OFF[NTOT + 1];
__device__ __align__(256) int g_CUR[NTOT + 1];
__device__ __align__(256) int g_EIX[ETOT];
__device__ __align__(256) int g_BS[256];
__device__ int g_flags[3];

// ---------------- helpers ----------------

__device__ __forceinline__ float gelu_f(float x) {
    return 0.5f * x * (1.f + erff(x * 0.70710678118654752f));
}

// Split pair (v0,v1) into packed bf16x2 hi and lo parts (hi+lo ~= fp32).
__device__ __forceinline__ void split_pack(float v0, float v1,
                                           uint32_t& ph, uint32_t& pl) {
    __nv_bfloat162 h2 = __floats2bfloat162_rn(v0, v1);
    ph = *(uint32_t*)&h2;
    float h0 = __bfloat162float(h2.x), h1 = __bfloat162float(h2.y);
    __nv_bfloat162 l2 = __floats2bfloat162_rn(v0 - h0, v1 - h1);
    pl = *(uint32_t*)&l2;
}

__device__ __forceinline__ void mma_bf16(float c[4], const uint32_t a[4],
                                         uint32_t b0, uint32_t b1) {
    asm volatile(
        "mma.sync.aligned.m16n8k16.row.col.f32.bf16.bf16.f32 "
        "{%0,%1,%2,%3}, {%4,%5,%6,%7}, {%8,%9}, {%0,%1,%2,%3};"
        : "+f"(c[0]), "+f"(c[1]), "+f"(c[2]), "+f"(c[3])
        : "r"(a[0]), "r"(a[1]), "r"(a[2]), "r"(a[3]), "r"(b0), "r"(b1));
}

__device__ __forceinline__ int edge_src(const int* b, int e, int E, int lay) {
    return lay ? b[2 * e] : b[e];
}
__device__ __forceinline__ int edge_dst(const int* b, int e, int E, int lay) {
    return lay ? b[2 * e + 1] : b[E + e];
}

struct GB {
    const float* A[3];
    const float* W[3];
    const float* Bias[3];
    float*       C[3];
    const float* R[3];
    const float* S[3];
    const float* D[3];
    int M[3], K[3], lda[3], ldw[3], ldc[3];
    int H;
};

struct CSR {
    const int* p0[5]; const int* p1[5];
    int flg[5];
    int ecnt[5]; int ebase[6];
    int droff[5]; int ndv[5];
    int kroff[5]; int nsv[5];
};

// ---------------- kernels ----------------

__global__ void resolve_kernel(const int* __restrict__ t01,
                               const int* __restrict__ t34a,
                               const int* __restrict__ t34b)
{
    __shared__ int s[8];
    if (threadIdx.x < 8) s[threadIdx.x] = 0;
    __syncthreads();
    int ah1 = 0, ah2 = 0, aodd = 0, bh1 = 0, bh2 = 0, bodd = 0, ch1 = 0, cev = 0;
    for (int i = threadIdx.x; i < 200000; i += blockDim.x) {
        int va = t34a[i], vb = t34b[i];
        if (i < 100000) { ah1 = max(ah1, va); bh1 = max(bh1, vb); }
        else            { ah2 = max(ah2, va); bh2 = max(bh2, vb); }
        if (i & 1) { aodd = max(aodd, va); bodd = max(bodd, vb); }
    }
    for (int i = threadIdx.x; i < 500000; i += blockDim.x) {
        int vc = t01[i];
        if (i < 250000) ch1 = max(ch1, vc);
        if (!(i & 1))   cev = max(cev, vc);
    }
    atomicMax(&s[0], ah1); atomicMax(&s[1], ah2); atomicMax(&s[2], aodd);
    atomicMax(&s[3], bh1); atomicMax(&s[4], bh2); atomicMax(&s[5], bodd);
    atomicMax(&s[6], ch1); atomicMax(&s[7], cev);
    __syncthreads();
    if (threadIdx.x == 0) {
        int m4 = min(min(s[0], s[1]), min(s[3], s[4]));
        int layE2 = (m4 >= 10000) ? 1 : 0;
        g_flags[2] = layE2;
        g_flags[1] = layE2 ? ((s[2] >= 10000) ? 1 : 0)
                           : ((s[1] >= 10000) ? 1 : 0);
        int srcmax = layE2 ? s[7] : s[6];
        g_flags[0] = (srcmax >= 60000) ? 1 : 0;
    }
}

__global__ void csr_zero(int* __restrict__ cnt) {
    int i = blockIdx.x * blockDim.x + threadIdx.x;
    if (i <= NTOT) cnt[i] = 0;
}

__global__ void csr_hist(CSR c, int* __restrict__ cnt) {
    int tid = blockIdx.x * blockDim.x + threadIdx.x;
    if (tid >= ETOT) return;
    int e = 0;
#pragma unroll
    for (int k = 1; k < 5; k++) if (tid >= c.ebase[k]) e = k;
    int i = tid - c.ebase[e], E = c.ecnt[e];
    const int* base = g_flags[c.flg[e]] ? c.p1[e] : c.p0[e];
    int lay = g_flags[2];
    int d = min(max(edge_dst(base, i, E, lay), 0), c.ndv[e] - 1);
    atomicAdd(&cnt[c.droff[e] + d], 1);
}

__global__ void csr_reduce(const int* __restrict__ cnt, int* __restrict__ bsum) {
    __shared__ int sh[1024];
    int i = blockIdx.x * 1024 + threadIdx.x;
    sh[threadIdx.x] = (i < NTOT) ? cnt[i] : 0;
    __syncthreads();
    for (int o = 512; o > 0; o >>= 1) {
        if (threadIdx.x < o) sh[threadIdx.x] += sh[threadIdx.x + o];
        __syncthreads();
    }
    if (threadIdx.x == 0) bsum[blockIdx.x] = sh[0];
}

__global__ void csr_bscan(int* __restrict__ bsum, int* __restrict__ off, int nb) {
    __shared__ int sh[256];
    int t = threadIdx.x;
    int v = (t < nb) ? bsum[t] : 0;
    sh[t] = v;
    __syncthreads();
    for (int o = 1; o < 256; o <<= 1) {
        int u = (t >= o) ? sh[t - o] : 0;
        __syncthreads();
        sh[t] += u;
        __syncthreads();
    }
    if (t < nb) bsum[t] = sh[t] - v;
    if (t == 255) off[NTOT] = sh[255];
}

__global__ void csr_apply(int* __restrict__ cnt, const int* __restrict__ bsum,
                          int* __restrict__ off) {
    __shared__ int sh[1024];
    int i = blockIdx.x * 1024 + threadIdx.x;
    int v = (i < NTOT) ? cnt[i] : 0;
    sh[threadIdx.x] = v;
    __syncthreads();
    for (int o = 1; o < 1024; o <<= 1) {
        int u = (threadIdx.x >= o) ? sh[threadIdx.x - o] : 0;
        __syncthreads();
        sh[threadIdx.x] += u;
        __syncthreads();
    }
    if (i < NTOT) {
        int ex = bsum[blockIdx.x] + sh[threadIdx.x] - v;
        off[i] = ex; cnt[i] = ex;
    }
}

__global__ void csr_scatter(CSR c, int* __restrict__ cur, int* __restrict__ eix) {
    int tid = blockIdx.x * blockDim.x + threadIdx.x;
    if (tid >= ETOT) return;
    int e = 0;
#pragma unroll
    for (int k = 1; k < 5; k++) if (tid >= c.ebase[k]) e = k;
    int i = tid - c.ebase[e], E = c.ecnt[e];
    const int* base = g_flags[c.flg[e]] ? c.p1[e] : c.p0[e];
    int lay = g_flags[2];
    int s = min(max(edge_src(base, i, E, lay), 0), c.nsv[e] - 1);
    int d = min(max(edge_dst(base, i, E, lay), 0), c.ndv[e] - 1);
    int pos = atomicAdd(&cur[c.droff[e] + d], 1);
    eix[pos] = c.kroff[e] + s;
}

// Batched (z = node type) C = epilogue(actA(A) @ W + bias) via 3x bf16-split
// MMA m16n8k16 (hi*hi + hi*lo + lo*hi; fp32 accumulate).
// Block tile 128x64x32, register-prefetch pipeline. K % 32 == 0.
// If D[z] != null, A element (m, k) is pre-divided by D[m*H + k/16].
__global__ __launch_bounds__(256)
void gemm_bfx(GB gb, int geluA, int reluO)
{
    const int z = blockIdx.z;
    const int M = gb.M[z];
    const int m0 = blockIdx.y * 128;
    if (m0 >= M) return;
    const int K = gb.K[z], lda = gb.lda[z], ldw = gb.ldw[z], ldc = gb.ldc[z];
    const float* __restrict__ A = gb.A[z];
    const float* __restrict__ W = gb.W[z];
    const float* __restrict__ bias = gb.Bias[z];
    const float* __restrict__ resid = gb.R[z];
    const float* __restrict__ Dn = gb.D[z];
    const int H = gb.H;
    float* __restrict__ C = gb.C[z];

    __shared__ uint32_t APh[16][136], APl[16][136];   // [k-pair][m], pad->conflict-free
    __shared__ uint32_t BPh[64][20],  BPl[64][20];    // [n][k-pair]
    const int tid = threadIdx.x;
    const int lane = tid & 31, wid = tid >> 5;
    const int n0 = blockIdx.x * 64;
    const int moff = (wid & 3) * 32, noff = (wid >> 2) * 32;
    const int am = tid & 127, ak = (tid >> 7) * 16;   // A loader: row, k-base
    const int bk2 = (tid & 15) * 2, bn = (tid >> 4) * 4;  // B loader: 2 k-rows, 4 n
    const bool arow_ok = (m0 + am < M);

    float c[2][4][4];
#pragma unroll
    for (int mt = 0; mt < 2; mt++)
#pragma unroll
        for (int nt = 0; nt < 4; nt++)
#pragma unroll
            for (int i = 0; i < 4; i++) c[mt][nt][i] = 0.f;

    float4 ra[4], rb0, rb1;
    const float4 fz = make_float4(0.f, 0.f, 0.f, 0.f);

#define LDG_TILE(K0)                                                          \
    do {                                                                      \
        const float* ap = A + (size_t)(m0 + am) * lda + (K0) + ak;            \
        if (arow_ok) {                                                        \
            ra[0] = *(const float4*)(ap);      ra[1] = *(const float4*)(ap + 4); \
            ra[2] = *(const float4*)(ap + 8);  ra[3] = *(const float4*)(ap + 12);\
        } else { ra[0] = fz; ra[1] = fz; ra[2] = fz; ra[3] = fz; }             \
        if (Dn && arow_ok) {                                                  \
            float dn = __ldg(Dn + (size_t)(m0 + am) * H + (((K0) + ak) >> 4)); \
            float inv = 1.f / fmaxf(dn, 1e-16f);                              \
            _Pragma("unroll")                                                 \
            for (int j = 0; j < 4; j++) {                                     \
                ra[j].x *= inv; ra[j].y *= inv; ra[j].z *= inv; ra[j].w *= inv; \
            }                                                                 \
        }                                                                     \
        if (geluA) {                                                          \
            _Pragma("unroll")                                                 \
            for (int j = 0; j < 4; j++) {                                     \
                ra[j].x = gelu_f(ra[j].x); ra[j].y = gelu_f(ra[j].y);         \
                ra[j].z = gelu_f(ra[j].z); ra[j].w = gelu_f(ra[j].w);         \
            }                                                                 \
        }                                                                     \
        const float* bp0 = W + (size_t)((K0) + bk2) * ldw + n0 + bn;          \
        rb0 = *(const float4*)(bp0);                                          \
        rb1 = *(const float4*)(bp0 + ldw);                                    \
    } while (0)

    LDG_TILE(0);
    const int niter = K >> 5;
    for (int it = 0; it < niter; it++) {
        __syncthreads();
        // A: pack 16 k-values into 8 bf16x2 pairs (hi + lo)
#pragma unroll
        for (int j = 0; j < 4; j++) {
            uint32_t ph, pl;
            split_pack(ra[j].x, ra[j].y, ph, pl);
            APh[(ak >> 1) + 2*j + 0][am] = ph; APl[(ak >> 1) + 2*j + 0][am] = pl;
            split_pack(ra[j].z, ra[j].w, ph, pl);
            APh[(ak >> 1) + 2*j + 1][am] = ph; APl[(ak >> 1) + 2*j + 1][am] = pl;
        }
        // B: pack k-adjacent rows into bf16x2 pairs per n column
        {
            float r0c[4] = {rb0.x, rb0.y, rb0.z, rb0.w};
            float r1c[4] = {rb1.x, rb1.y, rb1.z, rb1.w};
#pragma unroll
            for (int j = 0; j < 4; j++) {
                uint32_t ph, pl;
                split_pack(r0c[j], r1c[j], ph, pl);
                BPh[bn + j][bk2 >> 1] = ph; BPl[bn + j][bk2 >> 1] = pl;
            }
        }
        __syncthreads();
        if (it + 1 < niter) LDG_TILE((it + 1) << 5);   // prefetch overlaps MMA
#pragma unroll
        for (int ks = 0; ks < 2; ks++) {               // two k16 steps per tile
            const int pr = ks * 8 + (lane & 3);
            uint32_t ah[2][4], al[2][4];
#pragma unroll
            for (int mt = 0; mt < 2; mt++) {
                int r = moff + mt * 16 + (lane >> 2);
                ah[mt][0] = APh[pr][r];     ah[mt][1] = APh[pr][r + 8];
                ah[mt][2] = APh[pr + 4][r]; ah[mt][3] = APh[pr + 4][r + 8];
                al[mt][0] = APl[pr][r];     al[mt][1] = APl[pr][r + 8];
                al[mt][2] = APl[pr + 4][r]; al[mt][3] = APl[pr + 4][r + 8];
            }
#pragma unroll
            for (int nt = 0; nt < 4; nt++) {
                int bc = noff + nt * 8 + (lane >> 2);
                uint32_t bh0 = BPh[bc][pr], bh1 = BPh[bc][pr + 4];
                uint32_t bl0 = BPl[bc][pr], bl1 = BPl[bc][pr + 4];
#pragma unroll
                for (int mt = 0; mt < 2; mt++) {
                    mma_bf16(c[mt][nt], al[mt], bh0, bh1);   // lo*hi
                    mma_bf16(c[mt][nt], ah[mt], bl0, bl1);   // hi*lo
                    mma_bf16(c[mt][nt], ah[mt], bh0, bh1);   // hi*hi
                }
            }
        }
    }
#undef LDG_TILE

    float sa = 0.f;
    if (resid) { float s = *gb.S[z]; sa = 1.f / (1.f + __expf(-s)); }
#pragma unroll
    for (int mt = 0; mt < 2; mt++) {
#pragma unroll
        for (int half = 0; half < 2; half++) {
            int cm = m0 + moff + mt * 16 + (lane >> 2) + half * 8;
            if (cm >= M) continue;
#pragma unroll
            for (int nt = 0; nt < 4; nt++) {
                int cn = n0 + noff + nt * 8 + (lane & 3) * 2;
                float v0 = c[mt][nt][half * 2 + 0] + bias[cn];
                float v1 = c[mt][nt][half * 2 + 1] + bias[cn + 1];
                if (reluO) { v0 = fmaxf(v0, 0.f); v1 = fmaxf(v1, 0.f); }
                if (resid) {
                    float2 r2 = *(const float2*)(resid + (size_t)cm * ldc + cn);
                    v0 = sa * v0 + (1.f - sa) * r2.x;
                    v1 = sa * v1 + (1.f - sa) * r2.y;
                }
                *(float2*)(C + (size_t)cm * ldc + cn) = make_float2(v0, v1);
            }
        }
    }
}

// Per-edge-type relation transform; prel[h]*0.25 folded into KR.
__global__ __launch_bounds__(256)
void relx_kernel(const float* __restrict__ KQV, int S, int foutp,
                 const float* __restrict__ krel, const float* __restrict__ vrel,
                 const float* __restrict__ prel,
                 float* __restrict__ KR, float* __restrict__ VR, int nsrc, int H)
{
    extern __shared__ float sh[];
    float* skr = sh;
    float* svr = sh + H * 256;
    for (int i = threadIdx.x; i < H * 256; i += blockDim.x) {
        skr[i] = krel[i]; svr[i] = vrel[i];
    }
    __syncthreads();
    const int fout = H << 4;
    int tid = blockIdx.x * blockDim.x + threadIdx.x;
    if (tid >= nsrc * fout) return;
    int n = tid / fout, c = tid - n * fout;
    int h = c >> 4, eo = c & 15;
    const float4* kin = (const float4*)(KQV + (size_t)n * S + h * 16);
    const float4* vin = (const float4*)(KQV + (size_t)n * S + 2 * foutp + h * 16);
    const float* km = skr + h * 256 + eo;
    const float* vm = svr + h * 256 + eo;
    float ak = 0.f, av = 0.f;
#pragma unroll
    for (int j = 0; j < 4; j++) {
        float4 k4 = kin[j], v4 = vin[j];
        const float* kmj = km + (j << 6);
        const float* vmj = vm + (j << 6);
        ak += k4.x * kmj[0] + k4.y * kmj[16] + k4.z * kmj[32] + k4.w * kmj[48];
        av += v4.x * vmj[0] + v4.y * vmj[16] + v4.z * vmj[32] + v4.w * vmj[48];
    }
    KR[tid] = ak * (__ldg(prel + h) * 0.25f);
    VR[tid] = av;
}

// CSR aggregation: dpw destinations per warp.
__global__ __launch_bounds__(256)
void agg_csr_kernel(const float* __restrict__ KQV, int S, int fout, int H, int dpw,
                    const float* __restrict__ KR, const float* __restrict__ VR,
                    float* __restrict__ DEN, float* __restrict__ AG)
{
    int gw = (blockIdx.x * blockDim.x + threadIdx.x) >> 5;
    const int lane = threadIdx.x & 31;
    const int sub = (dpw == 2) ? (lane >> 4) : 0;
    int w = gw * dpw + sub;
    if (w >= NTOT) return;
    const int li = (dpw == 2) ? (lane & 15) : lane;
    const int c4 = li * 4;
    const unsigned mask = (dpw == 2) ? (0xFFFFu << (sub * 16)) : 0xFFFFFFFFu;
    float4 q4 = *(const float4*)(KQV + (size_t)w * S + fout + c4);
    float4 acc = make_float4(0.f, 0.f, 0.f, 0.f);
    float den = 0.f;
    int b = __ldg(&g_OFF[w]), e = __ldg(&g_OFF[w + 1]);
    for (int idx = b; idx < e; idx++) {
        int r = __ldg(&g_EIX[idx]);
        float4 k4 = *(const float4*)(KR + (size_t)r * fout + c4);
        float p = q4.x * k4.x + q4.y * k4.y + q4.z * k4.z + q4.w * k4.w;
        p += __shfl_xor_sync(mask, p, 1);
        p += __shfl_xor_sync(mask, p, 2);
        float ex = __expf(p);
        float4 v4 = *(const float4*)(VR + (size_t)r * fout + c4);
        acc.x += ex * v4.x; acc.y += ex * v4.y;
        acc.z += ex * v4.z; acc.w += ex * v4.w;
        den += ex;
    }
    *(float4*)(AG + (size_t)w * fout + c4) = acc;
    if ((li & 3) == 0) DEN[(size_t)w * H + (li >> 2)] = den;
}

// ---------------- host orchestration ----------------

extern "C" void kernel_launch(void* const* d_in, const int* in_sizes, int n_in,
                              void* d_out, int out_size)
{
    static const long long ESIZE[30] = {
        25600000, 6400000, 320000,
        500000, 500000, 400000, 200000, 200000,
        32768, 128, 16384, 128, 8192, 128,
        147456, 1152, 10240, 10240, 40, 49152, 384, 3,
        73728, 576, 5120, 5120, 20, 12288, 192, 3
    };
    const void* P[30];
    bool got[30];
    for (int j = 0; j < 30; j++) { got[j] = false; P[j] = nullptr; }
    for (int i = 0; i < n_in; i++) {
        for (int j = 0; j < 30; j++) {
            if (!got[j] && (long long)in_sizes[i] == ESIZE[j]) {
                P[j] = d_in[i]; got[j] = true; break;
            }
        }
    }
    for (int j = 0; j < 30; j++) if (!got[j]) return;

    const float* x_in[3]  = {(const float*)P[0], (const float*)P[1], (const float*)P[2]};
    const int*   eptr[5]  = {(const int*)P[3], (const int*)P[4], (const int*)P[5],
                             (const int*)P[6], (const int*)P[7]};
    const float* lin_w[3] = {(const float*)P[8], (const float*)P[10], (const float*)P[12]};
    const float* lin_b[3] = {(const float*)P[9], (const float*)P[11], (const float*)P[13]};
    const float* kqv_w[2] = {(const float*)P[14], (const float*)P[22]};
    const float* kqv_b[2] = {(const float*)P[15], (const float*)P[23]};
    const float* krel[2]  = {(const float*)P[16], (const float*)P[24]};
    const float* vrel[2]  = {(const float*)P[17], (const float*)P[25]};
    const float* prel[2]  = {(const float*)P[18], (const float*)P[26]};
    const float* outw[2]  = {(const float*)P[19], (const float*)P[27]};
    const float* outb[2]  = {(const float*)P[20], (const float*)P[28]};
    const float* skipv[2] = {(const float*)P[21], (const float*)P[29]};

    float *X, *Y, *KQV, *KR, *VR, *Db, *AG;
    int *OFFp, *CURp, *EIXp, *BSp;
#define GETSYM(p, s) do { if (cudaGetSymbolAddress((void**)&(p), s) != cudaSuccess) return; } while (0)
    GETSYM(X,  g_X);  GETSYM(Y,  g_Y);  GETSYM(KQV, g_KQV);
    GETSYM(KR, g_KR); GETSYM(VR, g_VR);
    GETSYM(Db, g_DEN); GETSYM(AG, g_AGG);
    GETSYM(OFFp, g_OFF); GETSYM(CURp, g_CUR); GETSYM(EIXp, g_EIX); GETSYM(BSp, g_BS);
#undef GETSYM

    const int ntyp[3]  = {NPAPER, NAUTH, NINST};
    const int roff[3]  = {0, NPAPER, NPAPER + NAUTH};
    const int idim[3]  = {256, 128, 64};
    // EDGE_TYPES = [(1,0), (0,0), (0,1), (1,2), (2,1)]
    const int esrc[5]  = {1, 0, 0, 1, 2};
    const int edst[5]  = {0, 0, 1, 2, 1};
    const int ecnt[5]  = {250000, 250000, 200000, 100000, 100000};
    const int kroff[5] = {0, 50000, 150000, 250000, 300000};

    resolve_kernel<<<1, 1024>>>(eptr[0], eptr[3], eptr[4]);

    // ---- build CSR (dst -> KR-row list), shared by both layers ----
    {
        CSR c;
        int eb = 0;
        for (int e = 0; e < 5; e++) {
            c.p0[e] = eptr[e];
            c.p1[e] = (e == 0) ? eptr[1] : (e == 1) ? eptr[0]
                    : (e == 3) ? eptr[4] : (e == 4) ? eptr[3] : eptr[2];
            c.flg[e] = (e <= 2) ? 0 : 1;
            c.ecnt[e] = ecnt[e];
            c.ebase[e] = eb; eb += ecnt[e];
            c.droff[e] = roff[edst[e]]; c.ndv[e] = ntyp[edst[e]];
            c.kroff[e] = kroff[e];      c.nsv[e] = ntyp[esrc[e]];
        }
        c.ebase[5] = eb;
        csr_zero<<<(NTOT + 256) / 256, 256>>>(CURp);
        csr_hist<<<(ETOT + 255) / 256, 256>>>(c, CURp);
        csr_reduce<<<NBLK, 1024>>>(CURp, BSp);
        csr_bscan<<<1, 256>>>(BSp, OFFp, NBLK);
        csr_apply<<<NBLK, 1024>>>(CURp, BSp, OFFp);
        csr_scatter<<<(ETOT + 255) / 256, 256>>>(c, CURp, EIXp);
    }

    const int MAXMB = (NPAPER + 127) / 128;   // 782

    // ---- input projections: X = relu(x @ lin_w + lin_b) ----
    {
        GB gb; gb.H = 1;
        for (int t = 0; t < 3; t++) {
            gb.A[t] = x_in[t];  gb.lda[t] = idim[t];
            gb.W[t] = lin_w[t]; gb.ldw[t] = 128;
            gb.Bias[t] = lin_b[t];
            gb.C[t] = X + (size_t)roff[t] * 128; gb.ldc[t] = 128;
            gb.R[t] = nullptr; gb.S[t] = nullptr; gb.D[t] = nullptr;
            gb.M[t] = ntyp[t]; gb.K[t] = idim[t];
        }
        gemm_bfx<<<dim3(2, MAXMB, 3), 256>>>(gb, 0, 1);
    }

    for (int li = 0; li < 2; li++) {
        const int H = li ? 4 : 8;
        const int fout = H * 16;
        const int S = 3 * fout;
        const int dpw = li ? 2 : 1;
        const float* Xin = li ? Y : X;

        // fused kqv projection, batched over types
        {
            GB gb; gb.H = 1;
            for (int t = 0; t < 3; t++) {
                gb.A[t] = Xin + (size_t)roff[t] * 128; gb.lda[t] = 128;
                gb.W[t] = kqv_w[li] + (size_t)t * 128 * S; gb.ldw[t] = S;
                gb.Bias[t] = kqv_b[li] + t * S;
                gb.C[t] = KQV + (size_t)roff[t] * S; gb.ldc[t] = S;
                gb.R[t] = nullptr; gb.S[t] = nullptr; gb.D[t] = nullptr;
                gb.M[t] = ntyp[t]; gb.K[t] = 128;
            }
            gemm_bfx<<<dim3(S / 64, MAXMB, 3), 256>>>(gb, 0, 0);
        }

        // per-edge-type relation transforms (prel*0.25 folded into KR)
        for (int e = 0; e < 5; e++) {
            int ns = ntyp[esrc[e]];
            int tot = ns * fout;
            size_t shb = (size_t)2 * H * 256 * sizeof(float);
            relx_kernel<<<(tot + 255) / 256, 256, shb>>>(
                KQV + (size_t)roff[esrc[e]] * S, S, fout,
                krel[li] + e * H * 256, vrel[li] + e * H * 256,
                prel[li] + e * H,
                KR + (size_t)kroff[e] * fout, VR + (size_t)kroff[e] * fout, ns, H);
        }

        // CSR aggregation (dpw dsts per warp)
        {
            int nw = (NTOT + dpw - 1) / dpw;
            agg_csr_kernel<<<(nw * 32 + 255) / 256, 256>>>(
                KQV, S, fout, H, dpw, KR, VR, Db, AG);
        }

        // output projection (batched; normalizes A by den inside the load)
        if (li == 0) {
            GB gb; gb.H = H;
            for (int t = 0; t < 3; t++) {
                gb.A[t] = AG + (size_t)roff[t] * 128; gb.lda[t] = 128;
                gb.W[t] = outw[0] + (size_t)t * 128 * 128; gb.ldw[t] = 128;
                gb.Bias[t] = outb[0] + t * 128;
                gb.C[t] = Y + (size_t)roff[t] * 128; gb.ldc[t] = 128;
                gb.R[t] = Xin + (size_t)roff[t] * 128; gb.S[t] = skipv[0] + t;
                gb.D[t] = Db + (size_t)roff[t] * H;
                gb.M[t] = ntyp[t]; gb.K[t] = 128;
            }
            gemm_bfx<<<dim3(2, MAXMB, 3), 256>>>(gb, 1, 0);
        } else {
            const size_t ooff[3] = {0, (size_t)NPAPER * 64, (size_t)(NPAPER + NAUTH) * 64};
            const long long need[3] = {6400000LL, 9600000LL, 9920000LL};
            GB gb; gb.H = H;
            for (int t = 0; t < 3; t++) {
                gb.A[t] = AG + (size_t)roff[t] * 64; gb.lda[t] = 64;
                gb.W[t] = outw[1] + (size_t)t * 64 * 64; gb.ldw[t] = 64;
                gb.Bias[t] = outb[1] + t * 64;
                gb.C[t] = (float*)d_out + ooff[t]; gb.ldc[t] = 64;
                gb.R[t] = nullptr; gb.S[t] = nullptr;
                gb.D[t] = Db + (size_t)roff[t] * H;
                gb.M[t] = ((long long)out_size >= need[t]) ? ntyp[t] : 0;
                gb.K[t] = 64;
            }
            gemm_bfx<<<dim3(1, MAXMB, 3), 256>>>(gb, 1, 0);
        }
    }
}

// round 16
// speedup vs baseline: 1.5688x; 1.0384x over previous
#include <cuda_runtime.h>
#include <cuda_bf16.h>
#include <cstdint>

#define NPAPER 100000
#define NAUTH  50000
#define NINST  5000
#define NTOT   155000
#define SRCROWS 305000
#define ETOT   900000
#define NBLK   152   // ceil(NTOT/1024)

// ---------------- device scratch (no allocations allowed) ----------------
__device__ __align__(256) float g_X[(size_t)NTOT*128];
__device__ __align__(256) float g_Y[(size_t)NTOT*128];
__device__ __align__(256) float g_KQV[(size_t)NTOT*384];
__device__ __align__(256) float g_KV[(size_t)SRCROWS*256];  // interleaved [kr|vr]
__device__ __align__(256) float g_DEN[(size_t)NTOT*8];
__device__ __align__(256) float g_AGG[(size_t)NTOT*128];
__device__ __align__(256) int g_OFF[NTOT + 1];
__device__ __align__(256) int g_CUR[NTOT + 1];
__device__ __align__(256) int g_EIX[ETOT];
__device__ __align__(256) int g_BS[256];
__device__ int g_flags[3];

// ---------------- helpers ----------------

__device__ __forceinline__ float gelu_f(float x) {
    return 0.5f * x * (1.f + erff(x * 0.70710678118654752f));
}

__device__ __forceinline__ void split_pack(float v0, float v1,
                                           uint32_t& ph, uint32_t& pl) {
    __nv_bfloat162 h2 = __floats2bfloat162_rn(v0, v1);
    ph = *(uint32_t*)&h2;
    float h0 = __bfloat162float(h2.x), h1 = __bfloat162float(h2.y);
    __nv_bfloat162 l2 = __floats2bfloat162_rn(v0 - h0, v1 - h1);
    pl = *(uint32_t*)&l2;
}

__device__ __forceinline__ void mma_bf16(float c[4], const uint32_t a[4],
                                         uint32_t b0, uint32_t b1) {
    asm volatile(
        "mma.sync.aligned.m16n8k16.row.col.f32.bf16.bf16.f32 "
        "{%0,%1,%2,%3}, {%4,%5,%6,%7}, {%8,%9}, {%0,%1,%2,%3};"
        : "+f"(c[0]), "+f"(c[1]), "+f"(c[2]), "+f"(c[3])
        : "r"(a[0]), "r"(a[1]), "r"(a[2]), "r"(a[3]), "r"(b0), "r"(b1));
}

__device__ __forceinline__ int edge_src(const int* b, int e, int E, int lay) {
    return lay ? b[2 * e] : b[e];
}
__device__ __forceinline__ int edge_dst(const int* b, int e, int E, int lay) {
    return lay ? b[2 * e + 1] : b[E + e];
}

struct GB {
    const float* A[3];
    const float* W[3];
    const float* Bias[3];
    float*       C[3];
    const float* R[3];
    const float* S[3];
    const float* D[3];
    int M[3], K[3], lda[3], ldw[3], ldc[3];
    int H;
};

struct CSR {
    const int* p0[5]; const int* p1[5];
    int flg[5];
    int ecnt[5]; int ebase[6];
    int droff[5]; int ndv[5];
    int kroff[5]; int nsv[5];
};

// ---------------- kernels ----------------

__global__ void resolve_kernel(const int* __restrict__ t01,
                               const int* __restrict__ t34a,
                               const int* __restrict__ t34b)
{
    __shared__ int s[8];
    if (threadIdx.x < 8) s[threadIdx.x] = 0;
    __syncthreads();
    int ah1 = 0, ah2 = 0, aodd = 0, bh1 = 0, bh2 = 0, bodd = 0, ch1 = 0, cev = 0;
    for (int i = threadIdx.x; i < 200000; i += blockDim.x) {
        int va = t34a[i], vb = t34b[i];
        if (i < 100000) { ah1 = max(ah1, va); bh1 = max(bh1, vb); }
        else            { ah2 = max(ah2, va); bh2 = max(bh2, vb); }
        if (i & 1) { aodd = max(aodd, va); bodd = max(bodd, vb); }
    }
    for (int i = threadIdx.x; i < 500000; i += blockDim.x) {
        int vc = t01[i];
        if (i < 250000) ch1 = max(ch1, vc);
        if (!(i & 1))   cev = max(cev, vc);
    }
    atomicMax(&s[0], ah1); atomicMax(&s[1], ah2); atomicMax(&s[2], aodd);
    atomicMax(&s[3], bh1); atomicMax(&s[4], bh2); atomicMax(&s[5], bodd);
    atomicMax(&s[6], ch1); atomicMax(&s[7], cev);
    __syncthreads();
    if (threadIdx.x == 0) {
        int m4 = min(min(s[0], s[1]), min(s[3], s[4]));
        int layE2 = (m4 >= 10000) ? 1 : 0;
        g_flags[2] = layE2;
        g_flags[1] = layE2 ? ((s[2] >= 10000) ? 1 : 0)
                           : ((s[1] >= 10000) ? 1 : 0);
        int srcmax = layE2 ? s[7] : s[6];
        g_flags[0] = (srcmax >= 60000) ? 1 : 0;
    }
}

__global__ void csr_zero(int* __restrict__ cnt) {
    int i = blockIdx.x * blockDim.x + threadIdx.x;
    if (i <= NTOT) cnt[i] = 0;
}

__global__ void csr_hist(CSR c, int* __restrict__ cnt) {
    int tid = blockIdx.x * blockDim.x + threadIdx.x;
    if (tid >= ETOT) return;
    int e = 0;
#pragma unroll
    for (int k = 1; k < 5; k++) if (tid >= c.ebase[k]) e = k;
    int i = tid - c.ebase[e], E = c.ecnt[e];
    const int* base = g_flags[c.flg[e]] ? c.p1[e] : c.p0[e];
    int lay = g_flags[2];
    int d = min(max(edge_dst(base, i, E, lay), 0), c.ndv[e] - 1);
    atomicAdd(&cnt[c.droff[e] + d], 1);
}

__global__ void csr_reduce(const int* __restrict__ cnt, int* __restrict__ bsum) {
    __shared__ int sh[1024];
    int i = blockIdx.x * 1024 + threadIdx.x;
    sh[threadIdx.x] = (i < NTOT) ? cnt[i] : 0;
    __syncthreads();
    for (int o = 512; o > 0; o >>= 1) {
        if (threadIdx.x < o) sh[threadIdx.x] += sh[threadIdx.x + o];
        __syncthreads();
    }
    if (threadIdx.x == 0) bsum[blockIdx.x] = sh[0];
}

__global__ void csr_bscan(int* __restrict__ bsum, int* __restrict__ off, int nb) {
    __shared__ int sh[256];
    int t = threadIdx.x;
    int v = (t < nb) ? bsum[t] : 0;
    sh[t] = v;
    __syncthreads();
    for (int o = 1; o < 256; o <<= 1) {
        int u = (t >= o) ? sh[t - o] : 0;
        __syncthreads();
        sh[t] += u;
        __syncthreads();
    }
    if (t < nb) bsum[t] = sh[t] - v;
    if (t == 255) off[NTOT] = sh[255];
}

__global__ void csr_apply(int* __restrict__ cnt, const int* __restrict__ bsum,
                          int* __restrict__ off) {
    __shared__ int sh[1024];
    int i = blockIdx.x * 1024 + threadIdx.x;
    int v = (i < NTOT) ? cnt[i] : 0;
    sh[threadIdx.x] = v;
    __syncthreads();
    for (int o = 1; o < 1024; o <<= 1) {
        int u = (threadIdx.x >= o) ? sh[threadIdx.x - o] : 0;
        __syncthreads();
        sh[threadIdx.x] += u;
        __syncthreads();
    }
    if (i < NTOT) {
        int ex = bsum[blockIdx.x] + sh[threadIdx.x] - v;
        off[i] = ex; cnt[i] = ex;
    }
}

__global__ void csr_scatter(CSR c, int* __restrict__ cur, int* __restrict__ eix) {
    int tid = blockIdx.x * blockDim.x + threadIdx.x;
    if (tid >= ETOT) return;
    int e = 0;
#pragma unroll
    for (int k = 1; k < 5; k++) if (tid >= c.ebase[k]) e = k;
    int i = tid - c.ebase[e], E = c.ecnt[e];
    const int* base = g_flags[c.flg[e]] ? c.p1[e] : c.p0[e];
    int lay = g_flags[2];
    int s = min(max(edge_src(base, i, E, lay), 0), c.nsv[e] - 1);
    int d = min(max(edge_dst(base, i, E, lay), 0), c.ndv[e] - 1);
    int pos = atomicAdd(&cur[c.droff[e] + d], 1);
    eix[pos] = c.kroff[e] + s;
}

// Batched (z = node type) C = epilogue(actA(A) @ W + bias) via 3x bf16-split
// MMA m16n8k16. Block tile 128x64x32, register-prefetch pipeline. K % 32 == 0.
__global__ __launch_bounds__(256)
void gemm_bfx(GB gb, int geluA, int reluO)
{
    const int z = blockIdx.z;
    const int M = gb.M[z];
    const int m0 = blockIdx.y * 128;
    if (m0 >= M) return;
    const int K = gb.K[z], lda = gb.lda[z], ldw = gb.ldw[z], ldc = gb.ldc[z];
    const float* __restrict__ A = gb.A[z];
    const float* __restrict__ W = gb.W[z];
    const float* __restrict__ bias = gb.Bias[z];
    const float* __restrict__ resid = gb.R[z];
    const float* __restrict__ Dn = gb.D[z];
    const int H = gb.H;
    float* __restrict__ C = gb.C[z];

    __shared__ uint32_t APh[16][136], APl[16][136];
    __shared__ uint32_t BPh[64][20],  BPl[64][20];
    const int tid = threadIdx.x;
    const int lane = tid & 31, wid = tid >> 5;
    const int n0 = blockIdx.x * 64;
    const int moff = (wid & 3) * 32, noff = (wid >> 2) * 32;
    const int am = tid & 127, ak = (tid >> 7) * 16;
    const int bk2 = (tid & 15) * 2, bn = (tid >> 4) * 4;
    const bool arow_ok = (m0 + am < M);

    float c[2][4][4];
#pragma unroll
    for (int mt = 0; mt < 2; mt++)
#pragma unroll
        for (int nt = 0; nt < 4; nt++)
#pragma unroll
            for (int i = 0; i < 4; i++) c[mt][nt][i] = 0.f;

    float4 ra[4], rb0, rb1;
    const float4 fz = make_float4(0.f, 0.f, 0.f, 0.f);

#define LDG_TILE(K0)                                                          \
    do {                                                                      \
        const float* ap = A + (size_t)(m0 + am) * lda + (K0) + ak;            \
        if (arow_ok) {                                                        \
            ra[0] = *(const float4*)(ap);      ra[1] = *(const float4*)(ap + 4); \
            ra[2] = *(const float4*)(ap + 8);  ra[3] = *(const float4*)(ap + 12);\
        } else { ra[0] = fz; ra[1] = fz; ra[2] = fz; ra[3] = fz; }             \
        if (Dn && arow_ok) {                                                  \
            float dn = __ldg(Dn + (size_t)(m0 + am) * H + (((K0) + ak) >> 4)); \
            float inv = 1.f / fmaxf(dn, 1e-16f);                              \
            _Pragma("unroll")                                                 \
            for (int j = 0; j < 4; j++) {                                     \
                ra[j].x *= inv; ra[j].y *= inv; ra[j].z *= inv; ra[j].w *= inv; \
            }                                                                 \
        }                                                                     \
        if (geluA) {                                                          \
            _Pragma("unroll")                                                 \
            for (int j = 0; j < 4; j++) {                                     \
                ra[j].x = gelu_f(ra[j].x); ra[j].y = gelu_f(ra[j].y);         \
                ra[j].z = gelu_f(ra[j].z); ra[j].w = gelu_f(ra[j].w);         \
            }                                                                 \
        }                                                                     \
        const float* bp0 = W + (size_t)((K0) + bk2) * ldw + n0 + bn;          \
        rb0 = *(const float4*)(bp0);                                          \
        rb1 = *(const float4*)(bp0 + ldw);                                    \
    } while (0)

    LDG_TILE(0);
    const int niter = K >> 5;
    for (int it = 0; it < niter; it++) {
        __syncthreads();
#pragma unroll
        for (int j = 0; j < 4; j++) {
            uint32_t ph, pl;
            split_pack(ra[j].x, ra[j].y, ph, pl);
            APh[(ak >> 1) + 2*j + 0][am] = ph; APl[(ak >> 1) + 2*j + 0][am] = pl;
            split_pack(ra[j].z, ra[j].w, ph, pl);
            APh[(ak >> 1) + 2*j + 1][am] = ph; APl[(ak >> 1) + 2*j + 1][am] = pl;
        }
        {
            float r0c[4] = {rb0.x, rb0.y, rb0.z, rb0.w};
            float r1c[4] = {rb1.x, rb1.y, rb1.z, rb1.w};
#pragma unroll
            for (int j = 0; j < 4; j++) {
                uint32_t ph, pl;
                split_pack(r0c[j], r1c[j], ph, pl);
                BPh[bn + j][bk2 >> 1] = ph; BPl[bn + j][bk2 >> 1] = pl;
            }
        }
        __syncthreads();
        if (it + 1 < niter) LDG_TILE((it + 1) << 5);
#pragma unroll
        for (int ks = 0; ks < 2; ks++) {
            const int pr = ks * 8 + (lane & 3);
            uint32_t ah[2][4], al[2][4];
#pragma unroll
            for (int mt = 0; mt < 2; mt++) {
                int r = moff + mt * 16 + (lane >> 2);
                ah[mt][0] = APh[pr][r];     ah[mt][1] = APh[pr][r + 8];
                ah[mt][2] = APh[pr + 4][r]; ah[mt][3] = APh[pr + 4][r + 8];
                al[mt][0] = APl[pr][r];     al[mt][1] = APl[pr][r + 8];
                al[mt][2] = APl[pr + 4][r]; al[mt][3] = APl[pr + 4][r + 8];
            }
#pragma unroll
            for (int nt = 0; nt < 4; nt++) {
                int bc = noff + nt * 8 + (lane >> 2);
                uint32_t bh0 = BPh[bc][pr], bh1 = BPh[bc][pr + 4];
                uint32_t bl0 = BPl[bc][pr], bl1 = BPl[bc][pr + 4];
#pragma unroll
                for (int mt = 0; mt < 2; mt++) {
                    mma_bf16(c[mt][nt], al[mt], bh0, bh1);
                    mma_bf16(c[mt][nt], ah[mt], bl0, bl1);
                    mma_bf16(c[mt][nt], ah[mt], bh0, bh1);
                }
            }
        }
    }
#undef LDG_TILE

    float sa = 0.f;
    if (resid) { float s = *gb.S[z]; sa = 1.f / (1.f + __expf(-s)); }
#pragma unroll
    for (int mt = 0; mt < 2; mt++) {
#pragma unroll
        for (int half = 0; half < 2; half++) {
            int cm = m0 + moff + mt * 16 + (lane >> 2) + half * 8;
            if (cm >= M) continue;
#pragma unroll
            for (int nt = 0; nt < 4; nt++) {
                int cn = n0 + noff + nt * 8 + (lane & 3) * 2;
                float v0 = c[mt][nt][half * 2 + 0] + bias[cn];
                float v1 = c[mt][nt][half * 2 + 1] + bias[cn + 1];
                if (reluO) { v0 = fmaxf(v0, 0.f); v1 = fmaxf(v1, 0.f); }
                if (resid) {
                    float2 r2 = *(const float2*)(resid + (size_t)cm * ldc + cn);
                    v0 = sa * v0 + (1.f - sa) * r2.x;
                    v1 = sa * v1 + (1.f - sa) * r2.y;
                }
                *(float2*)(C + (size_t)cm * ldc + cn) = make_float2(v0, v1);
            }
        }
    }
}

// Per-edge-type relation transform; prel[h]*0.25 folded into KR.
// Writes interleaved KV rows: [kr(fout) | vr(fout)] per source row.
__global__ __launch_bounds__(256)
void relx_kernel(const float* __restrict__ KQV, int S, int foutp,
                 const float* __restrict__ krel, const float* __restrict__ vrel,
                 const float* __restrict__ prel,
                 float* __restrict__ KV, int nsrc, int H)
{
    extern __shared__ float sh[];
    float* skr = sh;
    float* svr = sh + H * 256;
    for (int i = threadIdx.x; i < H * 256; i += blockDim.x) {
        skr[i] = krel[i]; svr[i] = vrel[i];
    }
    __syncthreads();
    const int fout = H << 4;
    int tid = blockIdx.x * blockDim.x + threadIdx.x;
    if (tid >= nsrc * fout) return;
    int n = tid / fout, c = tid - n * fout;
    int h = c >> 4, eo = c & 15;
    const float4* kin = (const float4*)(KQV + (size_t)n * S + h * 16);
    const float4* vin = (const float4*)(KQV + (size_t)n * S + 2 * foutp + h * 16);
    const float* km = skr + h * 256 + eo;
    const float* vm = svr + h * 256 + eo;
    float ak = 0.f, av = 0.f;
#pragma unroll
    for (int j = 0; j < 4; j++) {
        float4 k4 = kin[j], v4 = vin[j];
        const float* kmj = km + (j << 6);
        const float* vmj = vm + (j << 6);
        ak += k4.x * kmj[0] + k4.y * kmj[16] + k4.z * kmj[32] + k4.w * kmj[48];
        av += v4.x * vmj[0] + v4.y * vmj[16] + v4.z * vmj[32] + v4.w * vmj[48];
    }
    float* row = KV + (size_t)n * (2 * fout);
    row[c] = ak * (__ldg(prel + h) * 0.25f);
    row[fout + c] = av;
}

// CSR aggregation over interleaved KV rows, 2-edge unrolled for MLP.
// dpw destinations per warp (1 for fout=128, 2 for fout=64).
__global__ __launch_bounds__(256)
void agg_csr_kernel(const float* __restrict__ KQV, int S, int fout, int H, int dpw,
                    const float* __restrict__ KV,
                    float* __restrict__ DEN, float* __restrict__ AG)
{
    int gw = (blockIdx.x * blockDim.x + threadIdx.x) >> 5;
    const int lane = threadIdx.x & 31;
    const int sub = (dpw == 2) ? (lane >> 4) : 0;
    int w = gw * dpw + sub;
    if (w >= NTOT) return;
    const int li = (dpw == 2) ? (lane & 15) : lane;
    const int c4 = li * 4;
    const unsigned mask = (dpw == 2) ? (0xFFFFu << (sub * 16)) : 0xFFFFFFFFu;
    const int krow = 2 * fout;
    float4 q4 = *(const float4*)(KQV + (size_t)w * S + fout + c4);
    float4 acc = make_float4(0.f, 0.f, 0.f, 0.f);
    float den = 0.f;
    int b = __ldg(&g_OFF[w]), e = __ldg(&g_OFF[w + 1]);
    int idx = b;
    for (; idx + 2 <= e; idx += 2) {
        int r0 = __ldg(&g_EIX[idx]);
        int r1 = __ldg(&g_EIX[idx + 1]);
        const float* row0 = KV + (size_t)r0 * krow;
        const float* row1 = KV + (size_t)r1 * krow;
        float4 k0 = *(const float4*)(row0 + c4);
        float4 k1 = *(const float4*)(row1 + c4);
        float4 v0 = *(const float4*)(row0 + fout + c4);
        float4 v1 = *(const float4*)(row1 + fout + c4);
        float p0 = q4.x * k0.x + q4.y * k0.y + q4.z * k0.z + q4.w * k0.w;
        float p1 = q4.x * k1.x + q4.y * k1.y + q4.z * k1.z + q4.w * k1.w;
        p0 += __shfl_xor_sync(mask, p0, 1);
        p1 += __shfl_xor_sync(mask, p1, 1);
        p0 += __shfl_xor_sync(mask, p0, 2);
        p1 += __shfl_xor_sync(mask, p1, 2);
        float e0 = __expf(p0), e1 = __expf(p1);
        acc.x += e0 * v0.x + e1 * v1.x;
        acc.y += e0 * v0.y + e1 * v1.y;
        acc.z += e0 * v0.z + e1 * v1.z;
        acc.w += e0 * v0.w + e1 * v1.w;
        den += e0 + e1;
    }
    if (idx < e) {
        int r = __ldg(&g_EIX[idx]);
        const float* row = KV + (size_t)r * krow;
        float4 k4 = *(const float4*)(row + c4);
        float4 v4 = *(const float4*)(row + fout + c4);
        float p = q4.x * k4.x + q4.y * k4.y + q4.z * k4.z + q4.w * k4.w;
        p += __shfl_xor_sync(mask, p, 1);
        p += __shfl_xor_sync(mask, p, 2);
        float ex = __expf(p);
        acc.x += ex * v4.x; acc.y += ex * v4.y;
        acc.z += ex * v4.z; acc.w += ex * v4.w;
        den += ex;
    }
    *(float4*)(AG + (size_t)w * fout + c4) = acc;
    if ((li & 3) == 0) DEN[(size_t)w * H + (li >> 2)] = den;
}

// ---------------- host orchestration ----------------

extern "C" void kernel_launch(void* const* d_in, const int* in_sizes, int n_in,
                              void* d_out, int out_size)
{
    static const long long ESIZE[30] = {
        25600000, 6400000, 320000,
        500000, 500000, 400000, 200000, 200000,
        32768, 128, 16384, 128, 8192, 128,
        147456, 1152, 10240, 10240, 40, 49152, 384, 3,
        73728, 576, 5120, 5120, 20, 12288, 192, 3
    };
    const void* P[30];
    bool got[30];
    for (int j = 0; j < 30; j++) { got[j] = false; P[j] = nullptr; }
    for (int i = 0; i < n_in; i++) {
        for (int j = 0; j < 30; j++) {
            if (!got[j] && (long long)in_sizes[i] == ESIZE[j]) {
                P[j] = d_in[i]; got[j] = true; break;
            }
        }
    }
    for (int j = 0; j < 30; j++) if (!got[j]) return;

    const float* x_in[3]  = {(const float*)P[0], (const float*)P[1], (const float*)P[2]};
    const int*   eptr[5]  = {(const int*)P[3], (const int*)P[4], (const int*)P[5],
                             (const int*)P[6], (const int*)P[7]};
    const float* lin_w[3] = {(const float*)P[8], (const float*)P[10], (const float*)P[12]};
    const float* lin_b[3] = {(const float*)P[9], (const float*)P[11], (const float*)P[13]};
    const float* kqv_w[2] = {(const float*)P[14], (const float*)P[22]};
    const float* kqv_b[2] = {(const float*)P[15], (const float*)P[23]};
    const float* krel[2]  = {(const float*)P[16], (const float*)P[24]};
    const float* vrel[2]  = {(const float*)P[17], (const float*)P[25]};
    const float* prel[2]  = {(const float*)P[18], (const float*)P[26]};
    const float* outw[2]  = {(const float*)P[19], (const float*)P[27]};
    const float* outb[2]  = {(const float*)P[20], (const float*)P[28]};
    const float* skipv[2] = {(const float*)P[21], (const float*)P[29]};

    float *X, *Y, *KQV, *KV, *Db, *AG;
    int *OFFp, *CURp, *EIXp, *BSp;
#define GETSYM(p, s) do { if (cudaGetSymbolAddress((void**)&(p), s) != cudaSuccess) return; } while (0)
    GETSYM(X,  g_X);  GETSYM(Y,  g_Y);  GETSYM(KQV, g_KQV);
    GETSYM(KV, g_KV);
    GETSYM(Db, g_DEN); GETSYM(AG, g_AGG);
    GETSYM(OFFp, g_OFF); GETSYM(CURp, g_CUR); GETSYM(EIXp, g_EIX); GETSYM(BSp, g_BS);
#undef GETSYM

    const int ntyp[3]  = {NPAPER, NAUTH, NINST};
    const int roff[3]  = {0, NPAPER, NPAPER + NAUTH};
    const int idim[3]  = {256, 128, 64};
    // EDGE_TYPES = [(1,0), (0,0), (0,1), (1,2), (2,1)]
    const int esrc[5]  = {1, 0, 0, 1, 2};
    const int edst[5]  = {0, 0, 1, 2, 1};
    const int ecnt[5]  = {250000, 250000, 200000, 100000, 100000};
    const int kroff[5] = {0, 50000, 150000, 250000, 300000};

    resolve_kernel<<<1, 1024>>>(eptr[0], eptr[3], eptr[4]);

    // ---- build CSR (dst -> KV-row list), shared by both layers ----
    {
        CSR c;
        int eb = 0;
        for (int e = 0; e < 5; e++) {
            c.p0[e] = eptr[e];
            c.p1[e] = (e == 0) ? eptr[1] : (e == 1) ? eptr[0]
                    : (e == 3) ? eptr[4] : (e == 4) ? eptr[3] : eptr[2];
            c.flg[e] = (e <= 2) ? 0 : 1;
            c.ecnt[e] = ecnt[e];
            c.ebase[e] = eb; eb += ecnt[e];
            c.droff[e] = roff[edst[e]]; c.ndv[e] = ntyp[edst[e]];
            c.kroff[e] = kroff[e];      c.nsv[e] = ntyp[esrc[e]];
        }
        c.ebase[5] = eb;
        csr_zero<<<(NTOT + 256) / 256, 256>>>(CURp);
        csr_hist<<<(ETOT + 255) / 256, 256>>>(c, CURp);
        csr_reduce<<<NBLK, 1024>>>(CURp, BSp);
        csr_bscan<<<1, 256>>>(BSp, OFFp, NBLK);
        csr_apply<<<NBLK, 1024>>>(CURp, BSp, OFFp);
        csr_scatter<<<(ETOT + 255) / 256, 256>>>(c, CURp, EIXp);
    }

    const int MAXMB = (NPAPER + 127) / 128;   // 782

    // ---- input projections: X = relu(x @ lin_w + lin_b) ----
    {
        GB gb; gb.H = 1;
        for (int t = 0; t < 3; t++) {
            gb.A[t] = x_in[t];  gb.lda[t] = idim[t];
            gb.W[t] = lin_w[t]; gb.ldw[t] = 128;
            gb.Bias[t] = lin_b[t];
            gb.C[t] = X + (size_t)roff[t] * 128; gb.ldc[t] = 128;
            gb.R[t] = nullptr; gb.S[t] = nullptr; gb.D[t] = nullptr;
            gb.M[t] = ntyp[t]; gb.K[t] = idim[t];
        }
        gemm_bfx<<<dim3(2, MAXMB, 3), 256>>>(gb, 0, 1);
    }

    for (int li = 0; li < 2; li++) {
        const int H = li ? 4 : 8;
        const int fout = H * 16;
        const int S = 3 * fout;
        const int dpw = li ? 2 : 1;
        const float* Xin = li ? Y : X;

        // fused kqv projection, batched over types
        {
            GB gb; gb.H = 1;
            for (int t = 0; t < 3; t++) {
                gb.A[t] = Xin + (size_t)roff[t] * 128; gb.lda[t] = 128;
                gb.W[t] = kqv_w[li] + (size_t)t * 128 * S; gb.ldw[t] = S;
                gb.Bias[t] = kqv_b[li] + t * S;
                gb.C[t] = KQV + (size_t)roff[t] * S; gb.ldc[t] = S;
                gb.R[t] = nullptr; gb.S[t] = nullptr; gb.D[t] = nullptr;
                gb.M[t] = ntyp[t]; gb.K[t] = 128;
            }
            gemm_bfx<<<dim3(S / 64, MAXMB, 3), 256>>>(gb, 0, 0);
        }

        // per-edge-type relation transforms (interleaved KV output)
        for (int e = 0; e < 5; e++) {
            int ns = ntyp[esrc[e]];
            int tot = ns * fout;
            size_t shb = (size_t)2 * H * 256 * sizeof(float);
            relx_kernel<<<(tot + 255) / 256, 256, shb>>>(
                KQV + (size_t)roff[esrc[e]] * S, S, fout,
                krel[li] + e * H * 256, vrel[li] + e * H * 256,
                prel[li] + e * H,
                KV + (size_t)kroff[e] * 2 * fout, ns, H);
        }

        // CSR aggregation (dpw dsts per warp, 2-edge unrolled)
        {
            int nw = (NTOT + dpw - 1) / dpw;
            agg_csr_kernel<<<(nw * 32 + 255) / 256, 256>>>(
                KQV, S, fout, H, dpw, KV, Db, AG);
        }

        // output projection (batched; normalizes A by den inside the load)
        if (li == 0) {
            GB gb; gb.H = H;
            for (int t = 0; t < 3; t++) {
                gb.A[t] = AG + (size_t)roff[t] * 128; gb.lda[t] = 128;
                gb.W[t] = outw[0] + (size_t)t * 128 * 128; gb.ldw[t] = 128;
                gb.Bias[t] = outb[0] + t * 128;
                gb.C[t] = Y + (size_t)roff[t] * 128; gb.ldc[t] = 128;
                gb.R[t] = Xin + (size_t)roff[t] * 128; gb.S[t] = skipv[0] + t;
                gb.D[t] = Db + (size_t)roff[t] * H;
                gb.M[t] = ntyp[t]; gb.K[t] = 128;
            }
            gemm_bfx<<<dim3(2, MAXMB, 3), 256>>>(gb, 1, 0);
        } else {
            const size_t ooff[3] = {0, (size_t)NPAPER * 64, (size_t)(NPAPER + NAUTH) * 64};
            const long long need[3] = {6400000LL, 9600000LL, 9920000LL};
            GB gb; gb.H = H;
            for (int t = 0; t < 3; t++) {
                gb.A[t] = AG + (size_t)roff[t] * 64; gb.lda[t] = 64;
                gb.W[t] = outw[1] + (size_t)t * 64 * 64; gb.ldw[t] = 64;
                gb.Bias[t] = outb[1] + t * 64;
                gb.C[t] = (float*)d_out + ooff[t]; gb.ldc[t] = 64;
                gb.R[t] = nullptr; gb.S[t] = nullptr;
                gb.D[t] = Db + (size_t)roff[t] * H;
                gb.M[t] = ((long long)out_size >= need[t]) ? ntyp[t] : 0;
                gb.K[t] = 64;
            }
            gemm_bfx<<<dim3(1, MAXMB, 3), 256>>>(gb, 1, 0);
        }
    }
}